// round 10
// baseline (speedup 1.0000x reference)
#include <cuda_runtime.h>
#include <math_constants.h>
#include <cstdint>

#define Bb 4
#define Ss 1024
#define Dd 1024
#define Hh 16
#define DKk 64
#define DFFf 4096
#define EPSl 1e-5f

#define X_ELEMS   ((size_t)Bb * Ss * Dd)
#define ATT_ELEMS ((size_t)Bb * Hh * Ss * Ss)

// ---------------- scratch ----------------
__device__ float g_q[X_ELEMS];
__device__ float g_k[X_ELEMS];
__device__ float g_v[X_ELEMS];
__device__ float g_ctx[X_ELEMS];
__device__ float g_t1[X_ELEMS];
__device__ float g_x1[X_ELEMS];
__device__ float g_x1r[X_ELEMS];
__device__ float g_xr[X_ELEMS];
__device__ float g_ffh[(size_t)Bb * Ss * DFFf];
__device__ float g_wqt[(size_t)Dd * Dd];
__device__ float g_wkt[(size_t)Dd * Dd];
__device__ float g_wvt[(size_t)Dd * Dd];
__device__ float g_wot[(size_t)Dd * Dd];
__device__ float g_w1t[(size_t)Dd * DFFf];
__device__ float g_w2t[(size_t)Dd * DFFf];
__device__ float g_attn_fb[ATT_ELEMS];
__device__ float g_x_fb[X_ELEMS];

// ---------------- helpers ----------------
__device__ __forceinline__ void cp_async16(void* smem_dst, const void* gsrc) {
    uint32_t s = (uint32_t)__cvta_generic_to_shared(smem_dst);
    asm volatile("cp.async.cg.shared.global [%0], [%1], 16;" :: "r"(s), "l"(gsrc));
}
__device__ __forceinline__ void cp_commit() {
    asm volatile("cp.async.commit_group;");
}
template<int N>
__device__ __forceinline__ void cp_wait() {
    asm volatile("cp.async.wait_group %0;" :: "n"(N));
}
__device__ __forceinline__ uint32_t f2tf(uint32_t x) {
    uint32_t r;
    asm("cvt.rna.tf32.f32 %0, %1;" : "=r"(r) : "f"(__uint_as_float(x)));
    return r;
}
__device__ __forceinline__ float tf32r(float x) {
    return __uint_as_float(f2tf(__float_as_uint(x)));
}
__device__ __forceinline__ void ldsm_x4(uint32_t r[4], uint32_t saddr) {
    asm volatile("ldmatrix.sync.aligned.m8n8.x4.shared.b16 {%0,%1,%2,%3}, [%4];"
                 : "=r"(r[0]), "=r"(r[1]), "=r"(r[2]), "=r"(r[3]) : "r"(saddr));
}
__device__ __forceinline__ void mma_tf32(float c[4], const uint32_t a[4], const uint32_t b[2]) {
    asm volatile(
        "mma.sync.aligned.m16n8k8.row.col.f32.tf32.tf32.f32 "
        "{%0,%1,%2,%3}, {%4,%5,%6,%7}, {%8,%9}, {%0,%1,%2,%3};"
        : "+f"(c[0]), "+f"(c[1]), "+f"(c[2]), "+f"(c[3])
        : "r"(a[0]), "r"(a[1]), "r"(a[2]), "r"(a[3]), "r"(b[0]), "r"(b[1]));
}

// ---------------- round x to tf32 ----------------
__global__ void round_kernel(const float4* __restrict__ in, float4* __restrict__ out, int n4) {
    int i = blockIdx.x * blockDim.x + threadIdx.x;
    if (i >= n4) return;
    float4 v = in[i];
    v.x = tf32r(v.x); v.y = tf32r(v.y); v.z = tf32r(v.z); v.w = tf32r(v.w);
    out[i] = v;
}

// ---------------- round + transpose weights: W[R][C] -> Wt[C][R] ----------------
__global__ void round_transpose_kernel(const float* __restrict__ in, float* __restrict__ out,
                                       int R, int C) {
    __shared__ float tile[32][33];
    const int c0 = blockIdx.x * 32, r0 = blockIdx.y * 32;
    const int tx = threadIdx.x, ty = threadIdx.y;   // 32 x 8
#pragma unroll
    for (int i = 0; i < 4; i++)
        tile[ty + i * 8][tx] = in[(size_t)(r0 + ty + i * 8) * C + c0 + tx];
    __syncthreads();
#pragma unroll
    for (int i = 0; i < 4; i++)
        out[(size_t)(c0 + ty + i * 8) * R + r0 + tx] = tf32r(tile[tx][ty + i * 8]);
}

// ========== fused scores + softmax + ctx (P@V) ===============================
// grid (Ss/32, B*H), 512 thr. attn[z][q0:q0+32][:] = softmax(Q K^T/8) written
// once; ctx[b][q0:q0+32][h*64:+64] = P @ V computed in the same CTA.
__global__ void __launch_bounds__(512, 1)
fused_attention(const float* __restrict__ Q, const float* __restrict__ K,
                const float* __restrict__ V, float* __restrict__ attn,
                float* __restrict__ ctx) {
    constexpr int CN = 128;
    constexpr int KST = 68;       // K/V smem row stride (floats)
    constexpr int PST = 132;      // P smem row stride
    constexpr int NCH = Ss / CN;  // 8
    constexpr int KBUF = 2 * CN * KST;   // 17408 floats

    extern __shared__ float smem[];
    float* Ksm = smem;                    // [2][CN][KST]
    float* Psm = smem + KBUF;             // [32][PST]
    float* Vsm = smem + KBUF + 32 * PST;  // [2][CN][KST]
    __shared__ float red[32][8];

    const int z = blockIdx.y;
    const int b = z >> 4, h = z & 15;
    const int q0 = blockIdx.x * 32;
    const float* Qb = Q + (size_t)b * Ss * Dd + (size_t)h * DKk;
    const float* Kb = K + (size_t)b * Ss * Dd + (size_t)h * DKk;
    const float* Vb = V + (size_t)b * Ss * Dd + (size_t)h * DKk;
    float* Ob = attn + (size_t)z * Ss * Ss;

    const int tid = threadIdx.x;
    const int warp = tid >> 5, lane = tid & 31;
    const int grp = lane >> 2, tig = lane & 3;
    const int wrow = warp >> 3;
    const int wcol = warp & 7;
    const int r0 = q0 + wrow * 16;

    uint32_t qf[8][4];
#pragma unroll
    for (int ks = 0; ks < 8; ks++) {
        const float* p0 = &Qb[(size_t)(r0 + grp) * Dd + ks * 8 + tig];
        const float* p1 = &Qb[(size_t)(r0 + grp + 8) * Dd + ks * 8 + tig];
        qf[ks][0] = __float_as_uint(p0[0]);
        qf[ks][1] = __float_as_uint(p1[0]);
        qf[ks][2] = __float_as_uint(p0[4]);
        qf[ks][3] = __float_as_uint(p1[4]);
    }

    auto copyK = [&](int stage, int chunk) {
#pragma unroll
        for (int i = 0; i < 4; i++) {
            int flat = tid + i * 512;
            int r = flat >> 4, c4 = flat & 15;
            cp_async16(&Ksm[stage * CN * KST + r * KST + c4 * 4],
                       &Kb[(size_t)(chunk * CN + r) * Dd + c4 * 4]);
        }
    };
    auto copyV = [&](int stage, int chunk) {
#pragma unroll
        for (int i = 0; i < 4; i++) {
            int flat = tid + i * 512;
            int r = flat >> 4, c4 = flat & 15;
            cp_async16(&Vsm[stage * CN * KST + r * KST + c4 * 4],
                       &Vb[(size_t)(chunk * CN + r) * Dd + c4 * 4]);
        }
    };

    const uint32_t ksm_base = (uint32_t)__cvta_generic_to_shared(Ksm);
    const uint32_t psm_base = (uint32_t)__cvta_generic_to_shared(Psm);
    // B-operand lane layout (two n-tiles, k0-3 / k4-7)
    const int kf_off = (wcol * 16 + ((lane >> 4) << 3) + (lane & 7)) * KST
                     + (((lane >> 3) & 1) << 2);
    // A-operand lane layout: lanes 8-15 -> rows+8 (k0-3), lanes 16-31 -> k+4
    const int pf_off = (wrow * 16 + ((lane >> 3) & 1) * 8 + (lane & 7)) * PST
                     + ((lane >> 4) ? 4 : 0);

    float acc[NCH][2][4];
#pragma unroll
    for (int c = 0; c < NCH; c++)
#pragma unroll
        for (int j = 0; j < 2; j++)
#pragma unroll
            for (int q = 0; q < 4; q++) acc[c][j][q] = 0.f;

    // ---- phase 1: scores ----
    copyK(0, 0); cp_commit();
    for (int c = 0; c < NCH; c++) {
        cp_wait<0>();
        __syncthreads();
        if (c + 1 < NCH) { copyK((c + 1) & 1, c + 1); cp_commit(); }
        const uint32_t cb = ksm_base + 4u * ((c & 1) * CN * KST + kf_off);
#pragma unroll
        for (int ks = 0; ks < 8; ks++) {
            uint32_t r[4];
            ldsm_x4(r, cb + 4u * (ks * 8));
            uint32_t bf0[2] = { r[0], r[1] };
            uint32_t bf1[2] = { r[2], r[3] };
            mma_tf32(acc[c][0], qf[ks], bf0);
            mma_tf32(acc[c][1], qf[ks], bf1);
        }
    }
    __syncthreads();

    // prefetch V chunks 0,1 (overlaps softmax reductions)
    copyV(0, 0); cp_commit();
    copyV(1, 1); cp_commit();

    // ---- phase 2: softmax ----
    float m0 = -CUDART_INF_F, m1 = -CUDART_INF_F;
#pragma unroll
    for (int c = 0; c < NCH; c++)
#pragma unroll
        for (int j = 0; j < 2; j++) {
            acc[c][j][0] *= 0.125f; acc[c][j][1] *= 0.125f;
            acc[c][j][2] *= 0.125f; acc[c][j][3] *= 0.125f;
            m0 = fmaxf(m0, fmaxf(acc[c][j][0], acc[c][j][1]));
            m1 = fmaxf(m1, fmaxf(acc[c][j][2], acc[c][j][3]));
        }
    m0 = fmaxf(m0, __shfl_xor_sync(~0u, m0, 1));
    m0 = fmaxf(m0, __shfl_xor_sync(~0u, m0, 2));
    m1 = fmaxf(m1, __shfl_xor_sync(~0u, m1, 1));
    m1 = fmaxf(m1, __shfl_xor_sync(~0u, m1, 2));
    if (tig == 0) {
        red[wrow * 16 + grp][wcol] = m0;
        red[wrow * 16 + grp + 8][wcol] = m1;
    }
    __syncthreads();
    m0 = red[wrow * 16 + grp][0];
    m1 = red[wrow * 16 + grp + 8][0];
#pragma unroll
    for (int w = 1; w < 8; w++) {
        m0 = fmaxf(m0, red[wrow * 16 + grp][w]);
        m1 = fmaxf(m1, red[wrow * 16 + grp + 8][w]);
    }
    __syncthreads();

    float s0 = 0.f, s1 = 0.f;
#pragma unroll
    for (int c = 0; c < NCH; c++)
#pragma unroll
        for (int j = 0; j < 2; j++) {
            acc[c][j][0] = __expf(acc[c][j][0] - m0);
            acc[c][j][1] = __expf(acc[c][j][1] - m0);
            acc[c][j][2] = __expf(acc[c][j][2] - m1);
            acc[c][j][3] = __expf(acc[c][j][3] - m1);
            s0 += acc[c][j][0] + acc[c][j][1];
            s1 += acc[c][j][2] + acc[c][j][3];
        }
    s0 += __shfl_xor_sync(~0u, s0, 1);
    s0 += __shfl_xor_sync(~0u, s0, 2);
    s1 += __shfl_xor_sync(~0u, s1, 1);
    s1 += __shfl_xor_sync(~0u, s1, 2);
    if (tig == 0) {
        red[wrow * 16 + grp][wcol] = s0;
        red[wrow * 16 + grp + 8][wcol] = s1;
    }
    __syncthreads();
    s0 = 0.f; s1 = 0.f;
#pragma unroll
    for (int w = 0; w < 8; w++) {
        s0 += red[wrow * 16 + grp][w];
        s1 += red[wrow * 16 + grp + 8][w];
    }
    const float i0 = 1.f / s0, i1 = 1.f / s1;

    // ---- phase 3: write attn + ctx = P @ V ----
    float* O0 = &Ob[(size_t)(r0 + grp) * Ss];
    float* O1 = &Ob[(size_t)(r0 + grp + 8) * Ss];
    const int n0v = wcol * 8 + grp;
    float ctxacc[4] = {0.f, 0.f, 0.f, 0.f};

#pragma unroll
    for (int c = 0; c < NCH; c++) {
#pragma unroll
        for (int j = 0; j < 2; j++) {
            int col = wcol * 16 + j * 8 + tig * 2;
            float p0 = acc[c][j][0] * i0, p1 = acc[c][j][1] * i0;
            float p2 = acc[c][j][2] * i1, p3 = acc[c][j][3] * i1;
            *(float2*)&O0[c * 128 + col] = make_float2(p0, p1);
            *(float2*)&O1[c * 128 + col] = make_float2(p2, p3);
            *(float2*)&Psm[(wrow * 16 + grp) * PST + col] =
                make_float2(tf32r(p0), tf32r(p1));
            *(float2*)&Psm[(wrow * 16 + grp + 8) * PST + col] =
                make_float2(tf32r(p2), tf32r(p3));
        }
        if (c < NCH - 1) cp_wait<1>(); else cp_wait<0>();
        __syncthreads();
        const float* Vc = &Vsm[(c & 1) * CN * KST];
#pragma unroll
        for (int ks = 0; ks < 16; ks++) {
            uint32_t apf[4];
            ldsm_x4(apf, psm_base + 4u * (pf_off + ks * 8));
            uint32_t bfv[2];
            bfv[0] = __float_as_uint(Vc[(ks * 8 + tig) * KST + n0v]);
            bfv[1] = __float_as_uint(Vc[(ks * 8 + tig + 4) * KST + n0v]);
            mma_tf32(ctxacc, apf, bfv);
        }
        __syncthreads();
        if (c + 2 < NCH) { copyV(c & 1, c + 2); cp_commit(); }
    }

    // ctx write (rounded; feeds Wo GEMM)
    {
        int row = q0 + wrow * 16 + grp;
        int colc = h * DKk + wcol * 8 + tig * 2;
        float* C0p = &ctx[(size_t)(b * Ss + row) * Dd + colc];
        float* C1p = &ctx[(size_t)(b * Ss + row + 8) * Dd + colc];
        *(float2*)C0p = make_float2(tf32r(ctxacc[0]), tf32r(ctxacc[1]));
        *(float2*)C1p = make_float2(tf32r(ctxacc[2]), tf32r(ctxacc[3]));
    }
}

// MODE: 0 = plain GEMM. 3 = QKV batched.
// TRANSB: B stored [n][k] -> ldsm fragment loads. ROUT: round epilogue output.
template<int BM, int BN, int WM, int WN, bool TRANSB, bool BIAS, bool RELU,
         int MODE, bool CVTA, bool ROUT>
__global__ void __launch_bounds__(256)
tf32_gemm(const float* __restrict__ A,
          const float* __restrict__ B0, const float* __restrict__ B1p, const float* __restrict__ B2p,
          const float* __restrict__ bias0, const float* __restrict__ bias1, const float* __restrict__ bias2,
          float* __restrict__ C0, float* __restrict__ C1p, float* __restrict__ C2p,
          int K, int lda, int ldb, int ldc, float scale) {
    constexpr int BK = 16;
    constexpr int STAGES = 4;
    constexpr int WCOLS = BN / WN;
    constexpr int AM = WM / 16;
    constexpr int BNT = WN / 8;
    constexpr int ASTRIDE = BK + 4;
    constexpr int BSTRIDE = TRANSB ? (BK + 4) : (BN + 4);
    constexpr int SA = BM * ASTRIDE;
    constexpr int SB = TRANSB ? (BN * ASTRIDE) : (BK * (BN + 4));
    constexpr int LDA_V = BM * BK / (4 * 256);
    constexpr int LDB_V = (TRANSB ? BN * BK : BK * BN) / (4 * 256);

    extern __shared__ float smem[];
    float* As = smem;
    float* Bs = smem + STAGES * SA;

    const int tid = threadIdx.x;
    const int warp = tid >> 5, lane = tid & 31;
    const int grp = lane >> 2, tig = lane & 3;
    const int wm = (warp / WCOLS) * WM;
    const int wn = (warp % WCOLS) * WN;
    const int row0 = blockIdx.y * BM;
    const int col0 = blockIdx.x * BN;
    const int z = blockIdx.z;

    const float* Bsel = B0;
    const float* biasSel = bias0;
    float* Csel = C0;
    if (MODE == 3) {
        if (z == 1) { Bsel = B1p; biasSel = bias1; Csel = C1p; }
        else if (z == 2) { Bsel = B2p; biasSel = bias2; Csel = C2p; }
    }

    const float* Ag = A;
    const float* Bg = Bsel;
    float* Cg = Csel;

    auto copyA = [&](int stage, int k0) {
#pragma unroll
        for (int i = 0; i < LDA_V; i++) {
            int flat = tid + i * 256;
            int r = flat >> 2, c4 = flat & 3;
            cp_async16(&As[stage * SA + r * ASTRIDE + c4 * 4],
                       &Ag[(size_t)(row0 + r) * lda + k0 + c4 * 4]);
        }
    };
    auto copyB = [&](int stage, int k0) {
#pragma unroll
        for (int i = 0; i < LDB_V; i++) {
            int flat = tid + i * 256;
            if (TRANSB) {
                int n = flat >> 2, c4 = flat & 3;
                cp_async16(&Bs[stage * SB + n * BSTRIDE + c4 * 4],
                           &Bg[(size_t)(col0 + n) * ldb + k0 + c4 * 4]);
            } else {
                constexpr int C4 = BN / 4;
                int r = flat / C4, c4 = flat % C4;
                cp_async16(&Bs[stage * SB + r * BSTRIDE + c4 * 4],
                           &Bg[(size_t)(k0 + r) * ldb + col0 + c4 * 4]);
            }
        }
    };

    const uint32_t as_base = (uint32_t)__cvta_generic_to_shared(As);
    const uint32_t bs_base = (uint32_t)__cvta_generic_to_shared(Bs);
    const int a_thr_off = (wm + ((lane >> 3) & 1) * 8 + (lane & 7)) * ASTRIDE
                        + ((lane >> 4) ? 4 : 0);
    const int b4_off = TRANSB
        ? (wn + ((lane >> 4) << 3) + (lane & 7)) * BSTRIDE + (((lane >> 3) & 1) << 2)
        : 0;

    float acc[AM][BNT][4];
#pragma unroll
    for (int i = 0; i < AM; i++)
#pragma unroll
        for (int j = 0; j < BNT; j++)
#pragma unroll
            for (int q = 0; q < 4; q++) acc[i][j][q] = 0.f;

    const int KT = K / BK;
    int fetch = 0;
    for (; fetch < STAGES - 1; fetch++) {
        copyA(fetch, fetch * BK);
        copyB(fetch, fetch * BK);
        cp_commit();
    }

    for (int kt = 0; kt < KT; kt++) {
        cp_wait<STAGES - 2>();
        __syncthreads();
        if (fetch < KT) {
            copyA(fetch % STAGES, fetch * BK);
            copyB(fetch % STAGES, fetch * BK);
            fetch++;
        }
        cp_commit();

        const int buf = kt % STAGES;
        const float* Bsb = &Bs[buf * SB];
#pragma unroll
        for (int ks = 0; ks < BK; ks += 8) {
            uint32_t af[AM][4];
            uint32_t bf[BNT][2];
#pragma unroll
            for (int i = 0; i < AM; i++) {
                uint32_t addr = as_base + 4u * (buf * SA + a_thr_off + i * 16 * ASTRIDE + ks);
                ldsm_x4(af[i], addr);
                if (CVTA) {
                    af[i][0] = f2tf(af[i][0]); af[i][1] = f2tf(af[i][1]);
                    af[i][2] = f2tf(af[i][2]); af[i][3] = f2tf(af[i][3]);
                }
            }
            if (TRANSB) {
#pragma unroll
                for (int j = 0; j < BNT; j += 2) {
                    uint32_t r[4];
                    ldsm_x4(r, bs_base + 4u * (buf * SB + b4_off + j * 8 * BSTRIDE + ks));
                    bf[j][0] = r[0]; bf[j][1] = r[1];
                    bf[j + 1][0] = r[2]; bf[j + 1][1] = r[3];
                }
            } else {
#pragma unroll
                for (int j = 0; j < BNT; j++) {
                    int n = wn + j * 8 + grp;
                    bf[j][0] = __float_as_uint(Bsb[(ks + tig) * BSTRIDE + n]);
                    bf[j][1] = __float_as_uint(Bsb[(ks + tig + 4) * BSTRIDE + n]);
                }
            }
#pragma unroll
            for (int i = 0; i < AM; i++)
#pragma unroll
                for (int j = 0; j < BNT; j++)
                    mma_tf32(acc[i][j], af[i], bf[j]);
        }
    }

#pragma unroll
    for (int i = 0; i < AM; i++) {
        int r1 = row0 + wm + i * 16 + grp;
        int r2 = r1 + 8;
#pragma unroll
        for (int j = 0; j < BNT; j++) {
            int cc = col0 + wn + j * 8 + tig * 2;
            float b0v = 0.f, b1v = 0.f;
            if (BIAS) { b0v = biasSel[cc]; b1v = biasSel[cc + 1]; }
            float v0 = acc[i][j][0] * scale + b0v;
            float v1 = acc[i][j][1] * scale + b1v;
            float v2 = acc[i][j][2] * scale + b0v;
            float v3 = acc[i][j][3] * scale + b1v;
            if (RELU) {
                v0 = fmaxf(v0, 0.f); v1 = fmaxf(v1, 0.f);
                v2 = fmaxf(v2, 0.f); v3 = fmaxf(v3, 0.f);
            }
            if (ROUT) {
                v0 = tf32r(v0); v1 = tf32r(v1); v2 = tf32r(v2); v3 = tf32r(v3);
            }
            *(float2*)&Cg[(size_t)r1 * ldc + cc] = make_float2(v0, v1);
            *(float2*)&Cg[(size_t)r2 * ldc + cc] = make_float2(v2, v3);
        }
    }
}

// ---------------- residual add + layernorm (dual output) ----------------------
__global__ void add_ln_kernel(const float* __restrict__ a,
                              const float* __restrict__ bres,
                              const float* __restrict__ g,
                              const float* __restrict__ be,
                              float* __restrict__ out,
                              float* __restrict__ out_r) {
    const size_t row = blockIdx.x;
    const float4* pa = (const float4*)(a + row * Dd);
    const float4* pb = (const float4*)(bres + row * Dd);
    float4* po = (float4*)(out + row * Dd);
    const int tid = threadIdx.x;  // 256
    __shared__ float red[8];
    float4 va = pa[tid], vb = pb[tid];
    float4 v = make_float4(va.x + vb.x, va.y + vb.y, va.z + vb.z, va.w + vb.w);
    float s = v.x + v.y + v.z + v.w;
#pragma unroll
    for (int o = 16; o > 0; o >>= 1) s += __shfl_xor_sync(~0u, s, o);
    if ((tid & 31) == 0) red[tid >> 5] = s;
    __syncthreads();
    s = red[tid & 7];
#pragma unroll
    for (int o = 4; o > 0; o >>= 1) s += __shfl_xor_sync(~0u, s, o);
    const float mu = s * (1.f / Dd);
    float q = (v.x - mu) * (v.x - mu) + (v.y - mu) * (v.y - mu)
            + (v.z - mu) * (v.z - mu) + (v.w - mu) * (v.w - mu);
#pragma unroll
    for (int o = 16; o > 0; o >>= 1) q += __shfl_xor_sync(~0u, q, o);
    __syncthreads();
    if ((tid & 31) == 0) red[tid >> 5] = q;
    __syncthreads();
    q = red[tid & 7];
#pragma unroll
    for (int o = 4; o > 0; o >>= 1) q += __shfl_xor_sync(~0u, q, o);
    const float inv = rsqrtf(q * (1.f / Dd) + EPSl);
    float4 vg = ((const float4*)g)[tid], vbe = ((const float4*)be)[tid];
    float4 r = make_float4((v.x - mu) * inv * vg.x + vbe.x,
                           (v.y - mu) * inv * vg.y + vbe.y,
                           (v.z - mu) * inv * vg.z + vbe.z,
                           (v.w - mu) * inv * vg.w + vbe.w);
    po[tid] = r;
    if (out_r) {
        float4 rr = make_float4(tf32r(r.x), tf32r(r.y), tf32r(r.z), tf32r(r.w));
        ((float4*)(out_r + row * Dd))[tid] = rr;
    }
}

// ---------------- launch -------------------------------------------------------
extern "C" void kernel_launch(void* const* d_in, const int* in_sizes, int n_in,
                              void* d_out, int out_size) {
    const float* x  = (const float*)d_in[0];
    const float* Wq = (const float*)d_in[1];
    const float* bq = (const float*)d_in[2];
    const float* Wk = (const float*)d_in[3];
    const float* bk = (const float*)d_in[4];
    const float* Wv = (const float*)d_in[5];
    const float* bv = (const float*)d_in[6];
    const float* Wo = (const float*)d_in[7];
    const float* bo = (const float*)d_in[8];
    const float* W1 = (const float*)d_in[9];
    const float* b1 = (const float*)d_in[10];
    const float* W2 = (const float*)d_in[11];
    const float* b2 = (const float*)d_in[12];
    const float* g1 = (const float*)d_in[13];
    const float* be1 = (const float*)d_in[14];
    const float* g2 = (const float*)d_in[15];
    const float* be2 = (const float*)d_in[16];

    float* q;    cudaGetSymbolAddress((void**)&q,    g_q);
    float* k;    cudaGetSymbolAddress((void**)&k,    g_k);
    float* v;    cudaGetSymbolAddress((void**)&v,    g_v);
    float* ctx;  cudaGetSymbolAddress((void**)&ctx,  g_ctx);
    float* t1;   cudaGetSymbolAddress((void**)&t1,   g_t1);
    float* x1;   cudaGetSymbolAddress((void**)&x1,   g_x1);
    float* x1r;  cudaGetSymbolAddress((void**)&x1r,  g_x1r);
    float* xr;   cudaGetSymbolAddress((void**)&xr,   g_xr);
    float* ffh;  cudaGetSymbolAddress((void**)&ffh,  g_ffh);
    float* wqt;  cudaGetSymbolAddress((void**)&wqt,  g_wqt);
    float* wkt;  cudaGetSymbolAddress((void**)&wkt,  g_wkt);
    float* wvt;  cudaGetSymbolAddress((void**)&wvt,  g_wvt);
    float* wot;  cudaGetSymbolAddress((void**)&wot,  g_wot);
    float* w1t;  cudaGetSymbolAddress((void**)&w1t,  g_w1t);
    float* w2t;  cudaGetSymbolAddress((void**)&w2t,  g_w2t);
    float* attn_fb; cudaGetSymbolAddress((void**)&attn_fb, g_attn_fb);
    float* x_fb;    cudaGetSymbolAddress((void**)&x_fb,    g_x_fb);

    float* out_x;
    float* out_attn;
    const size_t osz = (size_t)out_size;
    if (osz >= X_ELEMS + ATT_ELEMS) {
        out_x = (float*)d_out;
        out_attn = (float*)d_out + X_ELEMS;
    } else if (osz == ATT_ELEMS) {
        out_x = x_fb;
        out_attn = (float*)d_out;
    } else {
        out_x = (float*)d_out;
        out_attn = attn_fb;
    }

    const int M = Bb * Ss;  // 4096
    dim3 blk(256);

    const int smem_projT = 4 * (128 * 20 + 128 * 20) * 4;          // 81,920 B
    const int smem_fused = (2 * 128 * 68 + 32 * 132 + 2 * 128 * 68) * 4;  // 156,160 B

    auto* kqkv   = tf32_gemm<128,128,64,32,true, true,false,3,false,true>;
    auto* kproj  = tf32_gemm<128,128,64,32,true, true,false,0,false,false>;
    auto* kprojr = tf32_gemm<128,128,64,32,true, true,true, 0,false,true>;
    cudaFuncSetAttribute(kqkv,   cudaFuncAttributeMaxDynamicSharedMemorySize, smem_projT);
    cudaFuncSetAttribute(kproj,  cudaFuncAttributeMaxDynamicSharedMemorySize, smem_projT);
    cudaFuncSetAttribute(kprojr, cudaFuncAttributeMaxDynamicSharedMemorySize, smem_projT);
    cudaFuncSetAttribute(fused_attention,
                         cudaFuncAttributeMaxDynamicSharedMemorySize, smem_fused);

    // round x; round+transpose all weights
    round_kernel<<<(X_ELEMS / 4 + 255) / 256, blk>>>((const float4*)x, (float4*)xr, X_ELEMS / 4);
    dim3 tblk(32, 8);
    round_transpose_kernel<<<dim3(Dd/32, Dd/32), tblk>>>(Wq, wqt, Dd, Dd);
    round_transpose_kernel<<<dim3(Dd/32, Dd/32), tblk>>>(Wk, wkt, Dd, Dd);
    round_transpose_kernel<<<dim3(Dd/32, Dd/32), tblk>>>(Wv, wvt, Dd, Dd);
    round_transpose_kernel<<<dim3(Dd/32, Dd/32), tblk>>>(Wo, wot, Dd, Dd);
    round_transpose_kernel<<<dim3(DFFf/32, Dd/32), tblk>>>(W1, w1t, Dd, DFFf);
    round_transpose_kernel<<<dim3(Dd/32, DFFf/32), tblk>>>(W2, w2t, DFFf, Dd);

    // QKV projections (transposed weights [n][k], row stride Dd)
    kqkv<<<dim3(Dd/128, M/128, 3), blk, smem_projT>>>(
        xr, wqt, wkt, wvt, bq, bk, bv, q, k, v, Dd, Dd, Dd, Dd, 1.f);

    // fused scores + softmax + ctx
    fused_attention<<<dim3(Ss/32, Bb*Hh), 512, smem_fused>>>(q, k, v, out_attn, ctx);

    // output projection + LN1  (wot [n][k], row stride Dd)
    kproj<<<dim3(Dd/128, M/128), blk, smem_projT>>>(
        ctx, wot, nullptr, nullptr, bo, nullptr, nullptr,
        t1, nullptr, nullptr, Dd, Dd, Dd, Dd, 1.f);
    add_ln_kernel<<<M, blk>>>(x, t1, g1, be1, x1, x1r);

    // FFN1: w1t is [DFF][Dd] -> ldb = Dd
    kprojr<<<dim3(DFFf/128, M/128), blk, smem_projT>>>(
        x1r, w1t, nullptr, nullptr, b1, nullptr, nullptr,
        ffh, nullptr, nullptr, Dd, Dd, Dd, DFFf, 1.f);
    // FFN2: w2t is [Dd][DFFf] -> ldb = DFFf
    kproj<<<dim3(Dd/128, M/128), blk, smem_projT>>>(
        ffh, w2t, nullptr, nullptr, b2, nullptr, nullptr,
        t1, nullptr, nullptr, DFFf, DFFf, DFFf, Dd, 1.f);
    add_ln_kernel<<<M, blk>>>(x1, t1, g2, be2, out_x, nullptr);
}

// round 11
// speedup vs baseline: 1.0771x; 1.0771x over previous
#include <cuda_runtime.h>
#include <math_constants.h>
#include <cstdint>

#define Bb 4
#define Ss 1024
#define Dd 1024
#define Hh 16
#define DKk 64
#define DFFf 4096
#define EPSl 1e-5f

#define X_ELEMS   ((size_t)Bb * Ss * Dd)
#define ATT_ELEMS ((size_t)Bb * Hh * Ss * Ss)

// ---------------- scratch ----------------
__device__ float g_q[X_ELEMS];
__device__ float g_k[X_ELEMS];
__device__ float g_v[X_ELEMS];
__device__ float g_ctx[X_ELEMS];
__device__ float g_t1[X_ELEMS];
__device__ float g_x1[X_ELEMS];
__device__ float g_x1r[X_ELEMS];
__device__ float g_xr[X_ELEMS];
__device__ float g_ffh[(size_t)Bb * Ss * DFFf];
__device__ float g_wqt[(size_t)Dd * Dd];
__device__ float g_wkt[(size_t)Dd * Dd];
__device__ float g_wvt[(size_t)Dd * Dd];
__device__ float g_wot[(size_t)Dd * Dd];
__device__ float g_w1t[(size_t)Dd * DFFf];
__device__ float g_w2t[(size_t)Dd * DFFf];
__device__ float g_attn_fb[ATT_ELEMS];
__device__ float g_x_fb[X_ELEMS];

// ---------------- helpers ----------------
__device__ __forceinline__ void cp_async16(void* smem_dst, const void* gsrc) {
    uint32_t s = (uint32_t)__cvta_generic_to_shared(smem_dst);
    asm volatile("cp.async.cg.shared.global [%0], [%1], 16;" :: "r"(s), "l"(gsrc));
}
__device__ __forceinline__ void cp_commit() {
    asm volatile("cp.async.commit_group;");
}
template<int N>
__device__ __forceinline__ void cp_wait() {
    asm volatile("cp.async.wait_group %0;" :: "n"(N));
}
__device__ __forceinline__ uint32_t f2tf(uint32_t x) {
    uint32_t r;
    asm("cvt.rna.tf32.f32 %0, %1;" : "=r"(r) : "f"(__uint_as_float(x)));
    return r;
}
__device__ __forceinline__ float tf32r(float x) {
    return __uint_as_float(f2tf(__float_as_uint(x)));
}
__device__ __forceinline__ void ldsm_x4(uint32_t r[4], uint32_t saddr) {
    asm volatile("ldmatrix.sync.aligned.m8n8.x4.shared.b16 {%0,%1,%2,%3}, [%4];"
                 : "=r"(r[0]), "=r"(r[1]), "=r"(r[2]), "=r"(r[3]) : "r"(saddr));
}
__device__ __forceinline__ void mma_tf32(float c[4], const uint32_t a[4], const uint32_t b[2]) {
    asm volatile(
        "mma.sync.aligned.m16n8k8.row.col.f32.tf32.tf32.f32 "
        "{%0,%1,%2,%3}, {%4,%5,%6,%7}, {%8,%9}, {%0,%1,%2,%3};"
        : "+f"(c[0]), "+f"(c[1]), "+f"(c[2]), "+f"(c[3])
        : "r"(a[0]), "r"(a[1]), "r"(a[2]), "r"(a[3]), "r"(b[0]), "r"(b[1]));
}

// ---------------- round x to tf32 ----------------
__global__ void round_kernel(const float4* __restrict__ in, float4* __restrict__ out, int n4) {
    int i = blockIdx.x * blockDim.x + threadIdx.x;
    if (i >= n4) return;
    float4 v = in[i];
    v.x = tf32r(v.x); v.y = tf32r(v.y); v.z = tf32r(v.z); v.w = tf32r(v.w);
    out[i] = v;
}

// ---------------- batched round + transpose: 6 weights in one launch ----------
struct RtJobs {
    const float* in[6];
    float* out[6];
    int R[6];
    int C[6];
    int base[6];   // first flat tile index of job
};
__global__ void rt_batch_kernel(RtJobs jb) {
    __shared__ float tile[32][33];
    const int bx = blockIdx.x;
    int j = 0;
#pragma unroll
    for (int t = 1; t < 6; t++) if (bx >= jb.base[t]) j = t;
    const int tiles_x = jb.C[j] >> 5;     // tiles along C
    const int t = bx - jb.base[j];
    const int c0 = (t % tiles_x) * 32;
    const int r0 = (t / tiles_x) * 32;
    const float* in = jb.in[j];
    float* out = jb.out[j];
    const int R = jb.R[j], C = jb.C[j];
    const int tx = threadIdx.x, ty = threadIdx.y;   // 32 x 8
#pragma unroll
    for (int i = 0; i < 4; i++)
        tile[ty + i * 8][tx] = in[(size_t)(r0 + ty + i * 8) * C + c0 + tx];
    __syncthreads();
#pragma unroll
    for (int i = 0; i < 4; i++)
        out[(size_t)(c0 + ty + i * 8) * R + r0 + tx] = tf32r(tile[tx][ty + i * 8]);
}

// ================= fused scores + softmax (Q,K pre-rounded) ==================
__global__ void __launch_bounds__(512, 1)
fused_scores_softmax(const float* __restrict__ Q, const float* __restrict__ K,
                     float* __restrict__ attn) {
    constexpr int CN = 128;
    constexpr int KST = 68;       // 272B row stride, 16B-aligned
    constexpr int NCH = Ss / CN;

    extern __shared__ float Ksm[];    // [2][CN][KST]
    __shared__ float red[32][8];

    const int z = blockIdx.y;
    const int b = z >> 4, h = z & 15;
    const int q0 = blockIdx.x * 32;
    const float* Qb = Q + (size_t)b * Ss * Dd + (size_t)h * DKk;
    const float* Kb = K + (size_t)b * Ss * Dd + (size_t)h * DKk;
    float* Ob = attn + (size_t)z * Ss * Ss;

    const int tid = threadIdx.x;
    const int warp = tid >> 5, lane = tid & 31;
    const int grp = lane >> 2, tig = lane & 3;
    const int wrow = warp >> 3;
    const int wcol = warp & 7;
    const int r0 = q0 + wrow * 16;

    uint32_t qf[8][4];
#pragma unroll
    for (int ks = 0; ks < 8; ks++) {
        const float* p0 = &Qb[(size_t)(r0 + grp) * Dd + ks * 8 + tig];
        const float* p1 = &Qb[(size_t)(r0 + grp + 8) * Dd + ks * 8 + tig];
        qf[ks][0] = __float_as_uint(p0[0]);
        qf[ks][1] = __float_as_uint(p1[0]);
        qf[ks][2] = __float_as_uint(p0[4]);
        qf[ks][3] = __float_as_uint(p1[4]);
    }

    auto copyK = [&](int stage, int chunk) {
#pragma unroll
        for (int i = 0; i < 4; i++) {
            int flat = tid + i * 512;
            int r = flat >> 4, c4 = flat & 15;
            cp_async16(&Ksm[stage * CN * KST + r * KST + c4 * 4],
                       &Kb[(size_t)(chunk * CN + r) * Dd + c4 * 4]);
        }
    };

    const uint32_t ksm_base = (uint32_t)__cvta_generic_to_shared(Ksm);
    const int kf_off = (wcol * 16 + ((lane >> 4) << 3) + (lane & 7)) * KST
                     + (((lane >> 3) & 1) << 2);

    float acc[NCH][2][4];
#pragma unroll
    for (int c = 0; c < NCH; c++)
#pragma unroll
        for (int j = 0; j < 2; j++)
#pragma unroll
            for (int q = 0; q < 4; q++) acc[c][j][q] = 0.f;

    copyK(0, 0); cp_commit();
    for (int c = 0; c < NCH; c++) {
        cp_wait<0>();
        __syncthreads();
        if (c + 1 < NCH) { copyK((c + 1) & 1, c + 1); cp_commit(); }
        const uint32_t cb = ksm_base + 4u * ((c & 1) * CN * KST + kf_off);
#pragma unroll
        for (int ks = 0; ks < 8; ks++) {
            uint32_t r[4];
            ldsm_x4(r, cb + 4u * (ks * 8));
            uint32_t bf0[2] = { r[0], r[1] };
            uint32_t bf1[2] = { r[2], r[3] };
            mma_tf32(acc[c][0], qf[ks], bf0);
            mma_tf32(acc[c][1], qf[ks], bf1);
        }
    }
    __syncthreads();

    float m0 = -CUDART_INF_F, m1 = -CUDART_INF_F;
#pragma unroll
    for (int c = 0; c < NCH; c++)
#pragma unroll
        for (int j = 0; j < 2; j++) {
            acc[c][j][0] *= 0.125f; acc[c][j][1] *= 0.125f;
            acc[c][j][2] *= 0.125f; acc[c][j][3] *= 0.125f;
            m0 = fmaxf(m0, fmaxf(acc[c][j][0], acc[c][j][1]));
            m1 = fmaxf(m1, fmaxf(acc[c][j][2], acc[c][j][3]));
        }
    m0 = fmaxf(m0, __shfl_xor_sync(~0u, m0, 1));
    m0 = fmaxf(m0, __shfl_xor_sync(~0u, m0, 2));
    m1 = fmaxf(m1, __shfl_xor_sync(~0u, m1, 1));
    m1 = fmaxf(m1, __shfl_xor_sync(~0u, m1, 2));
    if (tig == 0) {
        red[wrow * 16 + grp][wcol] = m0;
        red[wrow * 16 + grp + 8][wcol] = m1;
    }
    __syncthreads();
    m0 = red[wrow * 16 + grp][0];
    m1 = red[wrow * 16 + grp + 8][0];
#pragma unroll
    for (int w = 1; w < 8; w++) {
        m0 = fmaxf(m0, red[wrow * 16 + grp][w]);
        m1 = fmaxf(m1, red[wrow * 16 + grp + 8][w]);
    }
    __syncthreads();

    float s0 = 0.f, s1 = 0.f;
#pragma unroll
    for (int c = 0; c < NCH; c++)
#pragma unroll
        for (int j = 0; j < 2; j++) {
            acc[c][j][0] = __expf(acc[c][j][0] - m0);
            acc[c][j][1] = __expf(acc[c][j][1] - m0);
            acc[c][j][2] = __expf(acc[c][j][2] - m1);
            acc[c][j][3] = __expf(acc[c][j][3] - m1);
            s0 += acc[c][j][0] + acc[c][j][1];
            s1 += acc[c][j][2] + acc[c][j][3];
        }
    s0 += __shfl_xor_sync(~0u, s0, 1);
    s0 += __shfl_xor_sync(~0u, s0, 2);
    s1 += __shfl_xor_sync(~0u, s1, 1);
    s1 += __shfl_xor_sync(~0u, s1, 2);
    if (tig == 0) {
        red[wrow * 16 + grp][wcol] = s0;
        red[wrow * 16 + grp + 8][wcol] = s1;
    }
    __syncthreads();
    s0 = 0.f; s1 = 0.f;
#pragma unroll
    for (int w = 0; w < 8; w++) {
        s0 += red[wrow * 16 + grp][w];
        s1 += red[wrow * 16 + grp + 8][w];
    }
    const float i0 = 1.f / s0, i1 = 1.f / s1;

    float* O0 = &Ob[(size_t)(r0 + grp) * Ss];
    float* O1 = &Ob[(size_t)(r0 + grp + 8) * Ss];
#pragma unroll
    for (int c = 0; c < NCH; c++)
#pragma unroll
        for (int j = 0; j < 2; j++) {
            int col = c * 128 + wcol * 16 + j * 8 + tig * 2;
            *(float2*)&O0[col] = make_float2(acc[c][j][0] * i0, acc[c][j][1] * i0);
            *(float2*)&O1[col] = make_float2(acc[c][j][2] * i1, acc[c][j][3] * i1);
        }
}

// MODE: 0 = plain GEMM. 2 = ctx. 3 = QKV batched.
// TRANSB: B stored [n][k] (pre-transposed weights) -> ldsm fragment loads.
// CVTA: rna-round A fragments. ROUT: round epilogue output.
template<int BM, int BN, int WM, int WN, bool TRANSB, bool BIAS, bool RELU,
         int MODE, bool CVTA, bool ROUT>
__global__ void __launch_bounds__(256)
tf32_gemm(const float* __restrict__ A,
          const float* __restrict__ B0, const float* __restrict__ B1p, const float* __restrict__ B2p,
          const float* __restrict__ bias0, const float* __restrict__ bias1, const float* __restrict__ bias2,
          float* __restrict__ C0, float* __restrict__ C1p, float* __restrict__ C2p,
          int K, int lda, int ldb, int ldc, float scale) {
    constexpr int BK = 16;
    constexpr int STAGES = 4;
    constexpr int WCOLS = BN / WN;
    constexpr int AM = WM / 16;
    constexpr int BNT = WN / 8;
    constexpr int ASTRIDE = BK + 4;
    constexpr int BSTRIDE = TRANSB ? (BK + 4) : (BN + 4);
    constexpr int SA = BM * ASTRIDE;
    constexpr int SB = TRANSB ? (BN * ASTRIDE) : (BK * (BN + 4));
    constexpr int LDA_V = BM * BK / (4 * 256);
    constexpr int LDB_V = (TRANSB ? BN * BK : BK * BN) / (4 * 256);

    extern __shared__ float smem[];
    float* As = smem;
    float* Bs = smem + STAGES * SA;

    const int tid = threadIdx.x;
    const int warp = tid >> 5, lane = tid & 31;
    const int grp = lane >> 2, tig = lane & 3;
    const int wm = (warp / WCOLS) * WM;
    const int wn = (warp % WCOLS) * WN;
    const int row0 = blockIdx.y * BM;
    const int col0 = blockIdx.x * BN;
    const int z = blockIdx.z;

    const float* Bsel = B0;
    const float* biasSel = bias0;
    float* Csel = C0;
    if (MODE == 3) {
        if (z == 1) { Bsel = B1p; biasSel = bias1; Csel = C1p; }
        else if (z == 2) { Bsel = B2p; biasSel = bias2; Csel = C2p; }
    }

    size_t offA = 0, offB = 0, offC = 0;
    if (MODE == 2) {
        size_t ho = (size_t)(z >> 4) * Ss * Dd + (size_t)(z & 15) * DKk;
        offA = (size_t)z * Ss * Ss; offB = ho; offC = ho;
    }
    const float* Ag = A + offA;
    const float* Bg = Bsel + offB;
    float* Cg = Csel + offC;

    auto copyA = [&](int stage, int k0) {
#pragma unroll
        for (int i = 0; i < LDA_V; i++) {
            int flat = tid + i * 256;
            int r = flat >> 2, c4 = flat & 3;
            cp_async16(&As[stage * SA + r * ASTRIDE + c4 * 4],
                       &Ag[(size_t)(row0 + r) * lda + k0 + c4 * 4]);
        }
    };
    auto copyB = [&](int stage, int k0) {
#pragma unroll
        for (int i = 0; i < LDB_V; i++) {
            int flat = tid + i * 256;
            if (TRANSB) {
                int n = flat >> 2, c4 = flat & 3;
                cp_async16(&Bs[stage * SB + n * BSTRIDE + c4 * 4],
                           &Bg[(size_t)(col0 + n) * ldb + k0 + c4 * 4]);
            } else {
                constexpr int C4 = BN / 4;
                int r = flat / C4, c4 = flat % C4;
                cp_async16(&Bs[stage * SB + r * BSTRIDE + c4 * 4],
                           &Bg[(size_t)(k0 + r) * ldb + col0 + c4 * 4]);
            }
        }
    };

    const uint32_t as_base = (uint32_t)__cvta_generic_to_shared(As);
    const uint32_t bs_base = (uint32_t)__cvta_generic_to_shared(Bs);
    const int a_thr_off = (wm + ((lane >> 3) & 1) * 8 + (lane & 7)) * ASTRIDE
                        + ((lane >> 4) ? 4 : 0);
    const int b4_off = TRANSB
        ? (wn + ((lane >> 4) << 3) + (lane & 7)) * BSTRIDE + (((lane >> 3) & 1) << 2)
        : 0;

    float acc[AM][BNT][4];
#pragma unroll
    for (int i = 0; i < AM; i++)
#pragma unroll
        for (int j = 0; j < BNT; j++)
#pragma unroll
            for (int q = 0; q < 4; q++) acc[i][j][q] = 0.f;

    const int KT = K / BK;
    int fetch = 0;
    for (; fetch < STAGES - 1; fetch++) {
        copyA(fetch, fetch * BK);
        copyB(fetch, fetch * BK);
        cp_commit();
    }

    for (int kt = 0; kt < KT; kt++) {
        cp_wait<STAGES - 2>();
        __syncthreads();
        if (fetch < KT) {
            copyA(fetch % STAGES, fetch * BK);
            copyB(fetch % STAGES, fetch * BK);
            fetch++;
        }
        cp_commit();

        const int buf = kt % STAGES;
        const float* Bsb = &Bs[buf * SB];
#pragma unroll
        for (int ks = 0; ks < BK; ks += 8) {
            uint32_t af[AM][4];
            uint32_t bf[BNT][2];
#pragma unroll
            for (int i = 0; i < AM; i++) {
                uint32_t addr = as_base + 4u * (buf * SA + a_thr_off + i * 16 * ASTRIDE + ks);
                ldsm_x4(af[i], addr);
                if (CVTA) {
                    af[i][0] = f2tf(af[i][0]); af[i][1] = f2tf(af[i][1]);
                    af[i][2] = f2tf(af[i][2]); af[i][3] = f2tf(af[i][3]);
                }
            }
            if (TRANSB) {
#pragma unroll
                for (int j = 0; j < BNT; j += 2) {
                    uint32_t r[4];
                    ldsm_x4(r, bs_base + 4u * (buf * SB + b4_off + j * 8 * BSTRIDE + ks));
                    bf[j][0] = r[0]; bf[j][1] = r[1];
                    bf[j + 1][0] = r[2]; bf[j + 1][1] = r[3];
                }
            } else {
#pragma unroll
                for (int j = 0; j < BNT; j++) {
                    int n = wn + j * 8 + grp;
                    bf[j][0] = __float_as_uint(Bsb[(ks + tig) * BSTRIDE + n]);
                    bf[j][1] = __float_as_uint(Bsb[(ks + tig + 4) * BSTRIDE + n]);
                }
            }
#pragma unroll
            for (int i = 0; i < AM; i++)
#pragma unroll
                for (int j = 0; j < BNT; j++)
                    mma_tf32(acc[i][j], af[i], bf[j]);
        }
    }

#pragma unroll
    for (int i = 0; i < AM; i++) {
        int r1 = row0 + wm + i * 16 + grp;
        int r2 = r1 + 8;
#pragma unroll
        for (int j = 0; j < BNT; j++) {
            int cc = col0 + wn + j * 8 + tig * 2;
            float b0v = 0.f, b1v = 0.f;
            if (BIAS) { b0v = biasSel[cc]; b1v = biasSel[cc + 1]; }
            float v0 = acc[i][j][0] * scale + b0v;
            float v1 = acc[i][j][1] * scale + b1v;
            float v2 = acc[i][j][2] * scale + b0v;
            float v3 = acc[i][j][3] * scale + b1v;
            if (RELU) {
                v0 = fmaxf(v0, 0.f); v1 = fmaxf(v1, 0.f);
                v2 = fmaxf(v2, 0.f); v3 = fmaxf(v3, 0.f);
            }
            if (ROUT) {
                v0 = tf32r(v0); v1 = tf32r(v1); v2 = tf32r(v2); v3 = tf32r(v3);
            }
            *(float2*)&Cg[(size_t)r1 * ldc + cc] = make_float2(v0, v1);
            *(float2*)&Cg[(size_t)r2 * ldc + cc] = make_float2(v2, v3);
        }
    }
}

// ---------------- residual add + layernorm (dual output) ----------------------
__global__ void add_ln_kernel(const float* __restrict__ a,
                              const float* __restrict__ bres,
                              const float* __restrict__ g,
                              const float* __restrict__ be,
                              float* __restrict__ out,
                              float* __restrict__ out_r) {
    const size_t row = blockIdx.x;
    const float4* pa = (const float4*)(a + row * Dd);
    const float4* pb = (const float4*)(bres + row * Dd);
    float4* po = (float4*)(out + row * Dd);
    const int tid = threadIdx.x;  // 256
    __shared__ float red[8];
    float4 va = pa[tid], vb = pb[tid];
    float4 v = make_float4(va.x + vb.x, va.y + vb.y, va.z + vb.z, va.w + vb.w);
    float s = v.x + v.y + v.z + v.w;
#pragma unroll
    for (int o = 16; o > 0; o >>= 1) s += __shfl_xor_sync(~0u, s, o);
    if ((tid & 31) == 0) red[tid >> 5] = s;
    __syncthreads();
    s = red[tid & 7];
#pragma unroll
    for (int o = 4; o > 0; o >>= 1) s += __shfl_xor_sync(~0u, s, o);
    const float mu = s * (1.f / Dd);
    float q = (v.x - mu) * (v.x - mu) + (v.y - mu) * (v.y - mu)
            + (v.z - mu) * (v.z - mu) + (v.w - mu) * (v.w - mu);
#pragma unroll
    for (int o = 16; o > 0; o >>= 1) q += __shfl_xor_sync(~0u, q, o);
    __syncthreads();
    if ((tid & 31) == 0) red[tid >> 5] = q;
    __syncthreads();
    q = red[tid & 7];
#pragma unroll
    for (int o = 4; o > 0; o >>= 1) q += __shfl_xor_sync(~0u, q, o);
    const float inv = rsqrtf(q * (1.f / Dd) + EPSl);
    float4 vg = ((const float4*)g)[tid], vbe = ((const float4*)be)[tid];
    float4 r = make_float4((v.x - mu) * inv * vg.x + vbe.x,
                           (v.y - mu) * inv * vg.y + vbe.y,
                           (v.z - mu) * inv * vg.z + vbe.z,
                           (v.w - mu) * inv * vg.w + vbe.w);
    po[tid] = r;
    if (out_r) {
        float4 rr = make_float4(tf32r(r.x), tf32r(r.y), tf32r(r.z), tf32r(r.w));
        ((float4*)(out_r + row * Dd))[tid] = rr;
    }
}

// ---------------- launch -------------------------------------------------------
extern "C" void kernel_launch(void* const* d_in, const int* in_sizes, int n_in,
                              void* d_out, int out_size) {
    const float* x  = (const float*)d_in[0];
    const float* Wq = (const float*)d_in[1];
    const float* bq = (const float*)d_in[2];
    const float* Wk = (const float*)d_in[3];
    const float* bk = (const float*)d_in[4];
    const float* Wv = (const float*)d_in[5];
    const float* bv = (const float*)d_in[6];
    const float* Wo = (const float*)d_in[7];
    const float* bo = (const float*)d_in[8];
    const float* W1 = (const float*)d_in[9];
    const float* b1 = (const float*)d_in[10];
    const float* W2 = (const float*)d_in[11];
    const float* b2 = (const float*)d_in[12];
    const float* g1 = (const float*)d_in[13];
    const float* be1 = (const float*)d_in[14];
    const float* g2 = (const float*)d_in[15];
    const float* be2 = (const float*)d_in[16];

    float* q;    cudaGetSymbolAddress((void**)&q,    g_q);
    float* k;    cudaGetSymbolAddress((void**)&k,    g_k);
    float* v;    cudaGetSymbolAddress((void**)&v,    g_v);
    float* ctx;  cudaGetSymbolAddress((void**)&ctx,  g_ctx);
    float* t1;   cudaGetSymbolAddress((void**)&t1,   g_t1);
    float* x1;   cudaGetSymbolAddress((void**)&x1,   g_x1);
    float* x1r;  cudaGetSymbolAddress((void**)&x1r,  g_x1r);
    float* xr;   cudaGetSymbolAddress((void**)&xr,   g_xr);
    float* ffh;  cudaGetSymbolAddress((void**)&ffh,  g_ffh);
    float* wqt;  cudaGetSymbolAddress((void**)&wqt,  g_wqt);
    float* wkt;  cudaGetSymbolAddress((void**)&wkt,  g_wkt);
    float* wvt;  cudaGetSymbolAddress((void**)&wvt,  g_wvt);
    float* wot;  cudaGetSymbolAddress((void**)&wot,  g_wot);
    float* w1t;  cudaGetSymbolAddress((void**)&w1t,  g_w1t);
    float* w2t;  cudaGetSymbolAddress((void**)&w2t,  g_w2t);
    float* attn_fb; cudaGetSymbolAddress((void**)&attn_fb, g_attn_fb);
    float* x_fb;    cudaGetSymbolAddress((void**)&x_fb,    g_x_fb);

    float* out_x;
    float* out_attn;
    const size_t osz = (size_t)out_size;
    if (osz >= X_ELEMS + ATT_ELEMS) {
        out_x = (float*)d_out;
        out_attn = (float*)d_out + X_ELEMS;
    } else if (osz == ATT_ELEMS) {
        out_x = x_fb;
        out_attn = (float*)d_out;
    } else {
        out_x = (float*)d_out;
        out_attn = attn_fb;
    }

    const int M = Bb * Ss;  // 4096
    dim3 blk(256);

    const int smem_projT = 4 * (128 * 20 + 128 * 20) * 4;  // 81,920 B
    const int smem_ctx   = 4 * (128 * 20 + 16 * 68) * 4;   // 58,368 B
    const int smem_fused = 2 * 128 * 68 * 4;                // 69,632 B

    auto* kqkv   = tf32_gemm<128,128,64,32,true, true,false,3,false,true>;
    auto* kproj  = tf32_gemm<128,128,64,32,true, true,false,0,false,false>;
    auto* kprojr = tf32_gemm<128,128,64,32,true, true,true, 0,false,true>;
    auto* kctx   = tf32_gemm<128,64,64,16,false,false,false,2,true, true>;
    cudaFuncSetAttribute(kqkv,   cudaFuncAttributeMaxDynamicSharedMemorySize, smem_projT);
    cudaFuncSetAttribute(kproj,  cudaFuncAttributeMaxDynamicSharedMemorySize, smem_projT);
    cudaFuncSetAttribute(kprojr, cudaFuncAttributeMaxDynamicSharedMemorySize, smem_projT);
    cudaFuncSetAttribute(kctx,   cudaFuncAttributeMaxDynamicSharedMemorySize, smem_ctx);
    cudaFuncSetAttribute(fused_scores_softmax,
                         cudaFuncAttributeMaxDynamicSharedMemorySize, smem_fused);

    // round x; round+transpose all 6 weights in ONE launch
    round_kernel<<<(X_ELEMS / 4 + 255) / 256, blk>>>((const float4*)x, (float4*)xr, X_ELEMS / 4);
    {
        RtJobs jb;
        const float* ins[6] = { Wq, Wk, Wv, Wo, W1, W2 };
        float* outs[6]      = { wqt, wkt, wvt, wot, w1t, w2t };
        int Rs[6] = { Dd, Dd, Dd, Dd, Dd, DFFf };
        int Cs[6] = { Dd, Dd, Dd, Dd, DFFf, Dd };
        int base = 0;
        for (int j = 0; j < 6; j++) {
            jb.in[j] = ins[j]; jb.out[j] = outs[j];
            jb.R[j] = Rs[j]; jb.C[j] = Cs[j]; jb.base[j] = base;
            base += (Rs[j] / 32) * (Cs[j] / 32);
        }
        dim3 tblk(32, 8);
        rt_batch_kernel<<<base, tblk>>>(jb);   // base = 12288 tiles
    }

    // QKV projections (transposed weights [n][k], row stride Dd)
    kqkv<<<dim3(Dd/128, M/128, 3), blk, smem_projT>>>(
        xr, wqt, wkt, wvt, bq, bk, bv, q, k, v, Dd, Dd, Dd, Dd, 1.f);

    // fused scores + softmax
    fused_scores_softmax<<<dim3(Ss/32, Bb*Hh), 512, smem_fused>>>(q, k, out_attn);

    // ctx: attn (unrounded -> CVTA) @ V (rounded); output rounded
    kctx<<<dim3(1, Ss/128, Bb*Hh), blk, smem_ctx>>>(
        out_attn, v, nullptr, nullptr, nullptr, nullptr, nullptr,
        ctx, nullptr, nullptr, Ss, Ss, Dd, Dd, 1.f);

    // output projection + LN1  (wot [n][k], row stride Dd)
    kproj<<<dim3(Dd/128, M/128), blk, smem_projT>>>(
        ctx, wot, nullptr, nullptr, bo, nullptr, nullptr,
        t1, nullptr, nullptr, Dd, Dd, Dd, Dd, 1.f);
    add_ln_kernel<<<M, blk>>>(x, t1, g1, be1, x1, x1r);

    // FFN1: w1t is [DFF][Dd] -> ldb = Dd (row stride), ldc = DFFf
    kprojr<<<dim3(DFFf/128, M/128), blk, smem_projT>>>(
        x1r, w1t, nullptr, nullptr, b1, nullptr, nullptr,
        ffh, nullptr, nullptr, Dd, Dd, Dd, DFFf, 1.f);
    // FFN2: w2t is [Dd][DFFf] -> ldb = DFFf (row stride), ldc = Dd
    kproj<<<dim3(Dd/128, M/128), blk, smem_projT>>>(
        ffh, w2t, nullptr, nullptr, b2, nullptr, nullptr,
        t1, nullptr, nullptr, DFFf, DFFf, DFFf, Dd, 1.f);
    add_ln_kernel<<<M, blk>>>(x1, t1, g2, be2, out_x, nullptr);
}

// round 12
// speedup vs baseline: 1.0937x; 1.0154x over previous
#include <cuda_runtime.h>
#include <math_constants.h>
#include <cstdint>

#define Bb 4
#define Ss 1024
#define Dd 1024
#define Hh 16
#define DKk 64
#define DFFf 4096
#define EPSl 1e-5f

#define X_ELEMS   ((size_t)Bb * Ss * Dd)
#define ATT_ELEMS ((size_t)Bb * Hh * Ss * Ss)

// ---------------- scratch ----------------
__device__ float g_q[X_ELEMS];
__device__ float g_k[X_ELEMS];
__device__ float g_v[X_ELEMS];
__device__ float g_ctx[X_ELEMS];
__device__ float g_t1[X_ELEMS];
__device__ float g_x1[X_ELEMS];
__device__ float g_x1r[X_ELEMS];
__device__ float g_xr[X_ELEMS];
__device__ float g_ffh[(size_t)Bb * Ss * DFFf];
__device__ float g_wqt[(size_t)Dd * Dd];
__device__ float g_wkt[(size_t)Dd * Dd];
__device__ float g_wvt[(size_t)Dd * Dd];
__device__ float g_wot[(size_t)Dd * Dd];
__device__ float g_w1t[(size_t)Dd * DFFf];
__device__ float g_w2t[(size_t)Dd * DFFf];
__device__ float g_attn_fb[ATT_ELEMS];
__device__ float g_x_fb[X_ELEMS];

// ---------------- helpers ----------------
__device__ __forceinline__ void cp_async16(void* smem_dst, const void* gsrc) {
    uint32_t s = (uint32_t)__cvta_generic_to_shared(smem_dst);
    asm volatile("cp.async.cg.shared.global [%0], [%1], 16;" :: "r"(s), "l"(gsrc));
}
__device__ __forceinline__ void cp_commit() {
    asm volatile("cp.async.commit_group;");
}
template<int N>
__device__ __forceinline__ void cp_wait() {
    asm volatile("cp.async.wait_group %0;" :: "n"(N));
}
__device__ __forceinline__ uint32_t f2tf(uint32_t x) {
    uint32_t r;
    asm("cvt.rna.tf32.f32 %0, %1;" : "=r"(r) : "f"(__uint_as_float(x)));
    return r;
}
__device__ __forceinline__ float tf32r(float x) {
    return __uint_as_float(f2tf(__float_as_uint(x)));
}
__device__ __forceinline__ void ldsm_x4(uint32_t r[4], uint32_t saddr) {
    asm volatile("ldmatrix.sync.aligned.m8n8.x4.shared.b16 {%0,%1,%2,%3}, [%4];"
                 : "=r"(r[0]), "=r"(r[1]), "=r"(r[2]), "=r"(r[3]) : "r"(saddr));
}
__device__ __forceinline__ void mma_tf32(float c[4], const uint32_t a[4], const uint32_t b[2]) {
    asm volatile(
        "mma.sync.aligned.m16n8k8.row.col.f32.tf32.tf32.f32 "
        "{%0,%1,%2,%3}, {%4,%5,%6,%7}, {%8,%9}, {%0,%1,%2,%3};"
        : "+f"(c[0]), "+f"(c[1]), "+f"(c[2]), "+f"(c[3])
        : "r"(a[0]), "r"(a[1]), "r"(a[2]), "r"(a[3]), "r"(b[0]), "r"(b[1]));
}

// ---------------- round x to tf32 ----------------
__global__ void round_kernel(const float4* __restrict__ in, float4* __restrict__ out, int n4) {
    int i = blockIdx.x * blockDim.x + threadIdx.x;
    if (i >= n4) return;
    float4 v = in[i];
    v.x = tf32r(v.x); v.y = tf32r(v.y); v.z = tf32r(v.z); v.w = tf32r(v.w);
    out[i] = v;
}

// ---------------- batched round + transpose: 6 weights in one launch ----------
struct RtJobs {
    const float* in[6];
    float* out[6];
    int R[6];
    int C[6];
    int base[6];
};
__global__ void rt_batch_kernel(RtJobs jb) {
    __shared__ float tile[32][33];
    const int bx = blockIdx.x;
    int j = 0;
#pragma unroll
    for (int t = 1; t < 6; t++) if (bx >= jb.base[t]) j = t;
    const int tiles_x = jb.C[j] >> 5;
    const int t = bx - jb.base[j];
    const int c0 = (t % tiles_x) * 32;
    const int r0 = (t / tiles_x) * 32;
    const float* in = jb.in[j];
    float* out = jb.out[j];
    const int R = jb.R[j], C = jb.C[j];
    const int tx = threadIdx.x, ty = threadIdx.y;   // 32 x 8
#pragma unroll
    for (int i = 0; i < 4; i++)
        tile[ty + i * 8][tx] = in[(size_t)(r0 + ty + i * 8) * C + c0 + tx];
    __syncthreads();
#pragma unroll
    for (int i = 0; i < 4; i++)
        out[(size_t)(c0 + ty + i * 8) * R + r0 + tx] = tf32r(tile[tx][ty + i * 8]);
}

// ================= fused scores + softmax (3-stage K pipeline) ================
__global__ void __launch_bounds__(512, 1)
fused_scores_softmax(const float* __restrict__ Q, const float* __restrict__ K,
                     float* __restrict__ attn) {
    constexpr int CN = 128;
    constexpr int KST = 68;       // 272B row stride, 16B-aligned
    constexpr int NCH = Ss / CN;  // 8
    constexpr int SK = 3;         // pipeline stages

    extern __shared__ float Ksm[];    // [SK][CN][KST]
    __shared__ float red[32][8];

    const int z = blockIdx.y;
    const int b = z >> 4, h = z & 15;
    const int q0 = blockIdx.x * 32;
    const float* Qb = Q + (size_t)b * Ss * Dd + (size_t)h * DKk;
    const float* Kb = K + (size_t)b * Ss * Dd + (size_t)h * DKk;
    float* Ob = attn + (size_t)z * Ss * Ss;

    const int tid = threadIdx.x;
    const int warp = tid >> 5, lane = tid & 31;
    const int grp = lane >> 2, tig = lane & 3;
    const int wrow = warp >> 3;
    const int wcol = warp & 7;
    const int r0 = q0 + wrow * 16;

    uint32_t qf[8][4];
#pragma unroll
    for (int ks = 0; ks < 8; ks++) {
        const float* p0 = &Qb[(size_t)(r0 + grp) * Dd + ks * 8 + tig];
        const float* p1 = &Qb[(size_t)(r0 + grp + 8) * Dd + ks * 8 + tig];
        qf[ks][0] = __float_as_uint(p0[0]);
        qf[ks][1] = __float_as_uint(p1[0]);
        qf[ks][2] = __float_as_uint(p0[4]);
        qf[ks][3] = __float_as_uint(p1[4]);
    }

    auto copyK = [&](int stage, int chunk) {
#pragma unroll
        for (int i = 0; i < 4; i++) {
            int flat = tid + i * 512;
            int r = flat >> 4, c4 = flat & 15;
            cp_async16(&Ksm[stage * CN * KST + r * KST + c4 * 4],
                       &Kb[(size_t)(chunk * CN + r) * Dd + c4 * 4]);
        }
    };

    const uint32_t ksm_base = (uint32_t)__cvta_generic_to_shared(Ksm);
    const int kf_off = (wcol * 16 + ((lane >> 4) << 3) + (lane & 7)) * KST
                     + (((lane >> 3) & 1) << 2);

    float acc[NCH][2][4];
#pragma unroll
    for (int c = 0; c < NCH; c++)
#pragma unroll
        for (int j = 0; j < 2; j++)
#pragma unroll
            for (int q = 0; q < 4; q++) acc[c][j][q] = 0.f;

    int fetch = 0;
    for (; fetch < SK - 1; fetch++) { copyK(fetch, fetch); cp_commit(); }

    for (int c = 0; c < NCH; c++) {
        cp_wait<SK - 2>();
        __syncthreads();
        if (fetch < NCH) { copyK(fetch % SK, fetch); fetch++; }
        cp_commit();
        const uint32_t cb = ksm_base + 4u * ((c % SK) * CN * KST + kf_off);
#pragma unroll
        for (int ks = 0; ks < 8; ks++) {
            uint32_t r[4];
            ldsm_x4(r, cb + 4u * (ks * 8));
            uint32_t bf0[2] = { r[0], r[1] };
            uint32_t bf1[2] = { r[2], r[3] };
            mma_tf32(acc[c][0], qf[ks], bf0);
            mma_tf32(acc[c][1], qf[ks], bf1);
        }
    }
    __syncthreads();

    float m0 = -CUDART_INF_F, m1 = -CUDART_INF_F;
#pragma unroll
    for (int c = 0; c < NCH; c++)
#pragma unroll
        for (int j = 0; j < 2; j++) {
            acc[c][j][0] *= 0.125f; acc[c][j][1] *= 0.125f;
            acc[c][j][2] *= 0.125f; acc[c][j][3] *= 0.125f;
            m0 = fmaxf(m0, fmaxf(acc[c][j][0], acc[c][j][1]));
            m1 = fmaxf(m1, fmaxf(acc[c][j][2], acc[c][j][3]));
        }
    m0 = fmaxf(m0, __shfl_xor_sync(~0u, m0, 1));
    m0 = fmaxf(m0, __shfl_xor_sync(~0u, m0, 2));
    m1 = fmaxf(m1, __shfl_xor_sync(~0u, m1, 1));
    m1 = fmaxf(m1, __shfl_xor_sync(~0u, m1, 2));
    if (tig == 0) {
        red[wrow * 16 + grp][wcol] = m0;
        red[wrow * 16 + grp + 8][wcol] = m1;
    }
    __syncthreads();
    m0 = red[wrow * 16 + grp][0];
    m1 = red[wrow * 16 + grp + 8][0];
#pragma unroll
    for (int w = 1; w < 8; w++) {
        m0 = fmaxf(m0, red[wrow * 16 + grp][w]);
        m1 = fmaxf(m1, red[wrow * 16 + grp + 8][w]);
    }
    __syncthreads();

    float s0 = 0.f, s1 = 0.f;
#pragma unroll
    for (int c = 0; c < NCH; c++)
#pragma unroll
        for (int j = 0; j < 2; j++) {
            acc[c][j][0] = __expf(acc[c][j][0] - m0);
            acc[c][j][1] = __expf(acc[c][j][1] - m0);
            acc[c][j][2] = __expf(acc[c][j][2] - m1);
            acc[c][j][3] = __expf(acc[c][j][3] - m1);
            s0 += acc[c][j][0] + acc[c][j][1];
            s1 += acc[c][j][2] + acc[c][j][3];
        }
    s0 += __shfl_xor_sync(~0u, s0, 1);
    s0 += __shfl_xor_sync(~0u, s0, 2);
    s1 += __shfl_xor_sync(~0u, s1, 1);
    s1 += __shfl_xor_sync(~0u, s1, 2);
    if (tig == 0) {
        red[wrow * 16 + grp][wcol] = s0;
        red[wrow * 16 + grp + 8][wcol] = s1;
    }
    __syncthreads();
    s0 = 0.f; s1 = 0.f;
#pragma unroll
    for (int w = 0; w < 8; w++) {
        s0 += red[wrow * 16 + grp][w];
        s1 += red[wrow * 16 + grp + 8][w];
    }
    const float i0 = 1.f / s0, i1 = 1.f / s1;

    float* O0 = &Ob[(size_t)(r0 + grp) * Ss];
    float* O1 = &Ob[(size_t)(r0 + grp + 8) * Ss];
#pragma unroll
    for (int c = 0; c < NCH; c++)
#pragma unroll
        for (int j = 0; j < 2; j++) {
            int col = c * 128 + wcol * 16 + j * 8 + tig * 2;
            *(float2*)&O0[col] = make_float2(acc[c][j][0] * i0, acc[c][j][1] * i0);
            *(float2*)&O1[col] = make_float2(acc[c][j][2] * i1, acc[c][j][3] * i1);
        }
}

// MODE: 0 = plain GEMM. 2 = ctx. 3 = QKV batched.
// TRANSB: B stored [n][k] (pre-transposed weights) -> ldsm fragment loads.
// CVTA: rna-round A fragments. ROUT: round epilogue output. STAGES: cp.async depth.
template<int BM, int BN, int WM, int WN, bool TRANSB, bool BIAS, bool RELU,
         int MODE, bool CVTA, bool ROUT, int STAGES>
__global__ void __launch_bounds__(256)
tf32_gemm(const float* __restrict__ A,
          const float* __restrict__ B0, const float* __restrict__ B1p, const float* __restrict__ B2p,
          const float* __restrict__ bias0, const float* __restrict__ bias1, const float* __restrict__ bias2,
          float* __restrict__ C0, float* __restrict__ C1p, float* __restrict__ C2p,
          int K, int lda, int ldb, int ldc, float scale) {
    constexpr int BK = 16;
    constexpr int WCOLS = BN / WN;
    constexpr int AM = WM / 16;
    constexpr int BNT = WN / 8;
    constexpr int ASTRIDE = BK + 4;
    constexpr int BSTRIDE = TRANSB ? (BK + 4) : (BN + 4);
    constexpr int SA = BM * ASTRIDE;
    constexpr int SB = TRANSB ? (BN * ASTRIDE) : (BK * (BN + 4));
    constexpr int LDA_V = BM * BK / (4 * 256);
    constexpr int LDB_V = (TRANSB ? BN * BK : BK * BN) / (4 * 256);

    extern __shared__ float smem[];
    float* As = smem;
    float* Bs = smem + STAGES * SA;

    const int tid = threadIdx.x;
    const int warp = tid >> 5, lane = tid & 31;
    const int grp = lane >> 2, tig = lane & 3;
    const int wm = (warp / WCOLS) * WM;
    const int wn = (warp % WCOLS) * WN;
    const int row0 = blockIdx.y * BM;
    const int col0 = blockIdx.x * BN;
    const int z = blockIdx.z;

    const float* Bsel = B0;
    const float* biasSel = bias0;
    float* Csel = C0;
    if (MODE == 3) {
        if (z == 1) { Bsel = B1p; biasSel = bias1; Csel = C1p; }
        else if (z == 2) { Bsel = B2p; biasSel = bias2; Csel = C2p; }
    }

    size_t offA = 0, offB = 0, offC = 0;
    if (MODE == 2) {
        size_t ho = (size_t)(z >> 4) * Ss * Dd + (size_t)(z & 15) * DKk;
        offA = (size_t)z * Ss * Ss; offB = ho; offC = ho;
    }
    const float* Ag = A + offA;
    const float* Bg = Bsel + offB;
    float* Cg = Csel + offC;

    auto copyA = [&](int stage, int k0) {
#pragma unroll
        for (int i = 0; i < LDA_V; i++) {
            int flat = tid + i * 256;
            int r = flat >> 2, c4 = flat & 3;
            cp_async16(&As[stage * SA + r * ASTRIDE + c4 * 4],
                       &Ag[(size_t)(row0 + r) * lda + k0 + c4 * 4]);
        }
    };
    auto copyB = [&](int stage, int k0) {
#pragma unroll
        for (int i = 0; i < LDB_V; i++) {
            int flat = tid + i * 256;
            if (TRANSB) {
                int n = flat >> 2, c4 = flat & 3;
                cp_async16(&Bs[stage * SB + n * BSTRIDE + c4 * 4],
                           &Bg[(size_t)(col0 + n) * ldb + k0 + c4 * 4]);
            } else {
                constexpr int C4 = BN / 4;
                int r = flat / C4, c4 = flat % C4;
                cp_async16(&Bs[stage * SB + r * BSTRIDE + c4 * 4],
                           &Bg[(size_t)(k0 + r) * ldb + col0 + c4 * 4]);
            }
        }
    };

    const uint32_t as_base = (uint32_t)__cvta_generic_to_shared(As);
    const uint32_t bs_base = (uint32_t)__cvta_generic_to_shared(Bs);
    const int a_thr_off = (wm + ((lane >> 3) & 1) * 8 + (lane & 7)) * ASTRIDE
                        + ((lane >> 4) ? 4 : 0);
    const int b4_off = TRANSB
        ? (wn + ((lane >> 4) << 3) + (lane & 7)) * BSTRIDE + (((lane >> 3) & 1) << 2)
        : 0;

    float acc[AM][BNT][4];
#pragma unroll
    for (int i = 0; i < AM; i++)
#pragma unroll
        for (int j = 0; j < BNT; j++)
#pragma unroll
            for (int q = 0; q < 4; q++) acc[i][j][q] = 0.f;

    const int KT = K / BK;
    int fetch = 0;
    for (; fetch < STAGES - 1; fetch++) {
        copyA(fetch, fetch * BK);
        copyB(fetch, fetch * BK);
        cp_commit();
    }

    for (int kt = 0; kt < KT; kt++) {
        cp_wait<STAGES - 2>();
        __syncthreads();
        if (fetch < KT) {
            copyA(fetch % STAGES, fetch * BK);
            copyB(fetch % STAGES, fetch * BK);
            fetch++;
        }
        cp_commit();

        const int buf = kt % STAGES;
        const float* Bsb = &Bs[buf * SB];
#pragma unroll
        for (int ks = 0; ks < BK; ks += 8) {
            uint32_t af[AM][4];
            uint32_t bf[BNT][2];
#pragma unroll
            for (int i = 0; i < AM; i++) {
                uint32_t addr = as_base + 4u * (buf * SA + a_thr_off + i * 16 * ASTRIDE + ks);
                ldsm_x4(af[i], addr);
                if (CVTA) {
                    af[i][0] = f2tf(af[i][0]); af[i][1] = f2tf(af[i][1]);
                    af[i][2] = f2tf(af[i][2]); af[i][3] = f2tf(af[i][3]);
                }
            }
            if (TRANSB) {
#pragma unroll
                for (int j = 0; j < BNT; j += 2) {
                    uint32_t r[4];
                    ldsm_x4(r, bs_base + 4u * (buf * SB + b4_off + j * 8 * BSTRIDE + ks));
                    bf[j][0] = r[0]; bf[j][1] = r[1];
                    bf[j + 1][0] = r[2]; bf[j + 1][1] = r[3];
                }
            } else {
#pragma unroll
                for (int j = 0; j < BNT; j++) {
                    int n = wn + j * 8 + grp;
                    bf[j][0] = __float_as_uint(Bsb[(ks + tig) * BSTRIDE + n]);
                    bf[j][1] = __float_as_uint(Bsb[(ks + tig + 4) * BSTRIDE + n]);
                }
            }
#pragma unroll
            for (int i = 0; i < AM; i++)
#pragma unroll
                for (int j = 0; j < BNT; j++)
                    mma_tf32(acc[i][j], af[i], bf[j]);
        }
    }

#pragma unroll
    for (int i = 0; i < AM; i++) {
        int r1 = row0 + wm + i * 16 + grp;
        int r2 = r1 + 8;
#pragma unroll
        for (int j = 0; j < BNT; j++) {
            int cc = col0 + wn + j * 8 + tig * 2;
            float b0v = 0.f, b1v = 0.f;
            if (BIAS) { b0v = biasSel[cc]; b1v = biasSel[cc + 1]; }
            float v0 = acc[i][j][0] * scale + b0v;
            float v1 = acc[i][j][1] * scale + b1v;
            float v2 = acc[i][j][2] * scale + b0v;
            float v3 = acc[i][j][3] * scale + b1v;
            if (RELU) {
                v0 = fmaxf(v0, 0.f); v1 = fmaxf(v1, 0.f);
                v2 = fmaxf(v2, 0.f); v3 = fmaxf(v3, 0.f);
            }
            if (ROUT) {
                v0 = tf32r(v0); v1 = tf32r(v1); v2 = tf32r(v2); v3 = tf32r(v3);
            }
            *(float2*)&Cg[(size_t)r1 * ldc + cc] = make_float2(v0, v1);
            *(float2*)&Cg[(size_t)r2 * ldc + cc] = make_float2(v2, v3);
        }
    }
}

// ---------------- residual add + layernorm (dual output) ----------------------
__global__ void add_ln_kernel(const float* __restrict__ a,
                              const float* __restrict__ bres,
                              const float* __restrict__ g,
                              const float* __restrict__ be,
                              float* __restrict__ out,
                              float* __restrict__ out_r) {
    const size_t row = blockIdx.x;
    const float4* pa = (const float4*)(a + row * Dd);
    const float4* pb = (const float4*)(bres + row * Dd);
    float4* po = (float4*)(out + row * Dd);
    const int tid = threadIdx.x;  // 256
    __shared__ float red[8];
    float4 va = pa[tid], vb = pb[tid];
    float4 v = make_float4(va.x + vb.x, va.y + vb.y, va.z + vb.z, va.w + vb.w);
    float s = v.x + v.y + v.z + v.w;
#pragma unroll
    for (int o = 16; o > 0; o >>= 1) s += __shfl_xor_sync(~0u, s, o);
    if ((tid & 31) == 0) red[tid >> 5] = s;
    __syncthreads();
    s = red[tid & 7];
#pragma unroll
    for (int o = 4; o > 0; o >>= 1) s += __shfl_xor_sync(~0u, s, o);
    const float mu = s * (1.f / Dd);
    float q = (v.x - mu) * (v.x - mu) + (v.y - mu) * (v.y - mu)
            + (v.z - mu) * (v.z - mu) + (v.w - mu) * (v.w - mu);
#pragma unroll
    for (int o = 16; o > 0; o >>= 1) q += __shfl_xor_sync(~0u, q, o);
    __syncthreads();
    if ((tid & 31) == 0) red[tid >> 5] = q;
    __syncthreads();
    q = red[tid & 7];
#pragma unroll
    for (int o = 4; o > 0; o >>= 1) q += __shfl_xor_sync(~0u, q, o);
    const float inv = rsqrtf(q * (1.f / Dd) + EPSl);
    float4 vg = ((const float4*)g)[tid], vbe = ((const float4*)be)[tid];
    float4 r = make_float4((v.x - mu) * inv * vg.x + vbe.x,
                           (v.y - mu) * inv * vg.y + vbe.y,
                           (v.z - mu) * inv * vg.z + vbe.z,
                           (v.w - mu) * inv * vg.w + vbe.w);
    po[tid] = r;
    if (out_r) {
        float4 rr = make_float4(tf32r(r.x), tf32r(r.y), tf32r(r.z), tf32r(r.w));
        ((float4*)(out_r + row * Dd))[tid] = rr;
    }
}

// ---------------- launch -------------------------------------------------------
extern "C" void kernel_launch(void* const* d_in, const int* in_sizes, int n_in,
                              void* d_out, int out_size) {
    const float* x  = (const float*)d_in[0];
    const float* Wq = (const float*)d_in[1];
    const float* bq = (const float*)d_in[2];
    const float* Wk = (const float*)d_in[3];
    const float* bk = (const float*)d_in[4];
    const float* Wv = (const float*)d_in[5];
    const float* bv = (const float*)d_in[6];
    const float* Wo = (const float*)d_in[7];
    const float* bo = (const float*)d_in[8];
    const float* W1 = (const float*)d_in[9];
    const float* b1 = (const float*)d_in[10];
    const float* W2 = (const float*)d_in[11];
    const float* b2 = (const float*)d_in[12];
    const float* g1 = (const float*)d_in[13];
    const float* be1 = (const float*)d_in[14];
    const float* g2 = (const float*)d_in[15];
    const float* be2 = (const float*)d_in[16];

    float* q;    cudaGetSymbolAddress((void**)&q,    g_q);
    float* k;    cudaGetSymbolAddress((void**)&k,    g_k);
    float* v;    cudaGetSymbolAddress((void**)&v,    g_v);
    float* ctx;  cudaGetSymbolAddress((void**)&ctx,  g_ctx);
    float* t1;   cudaGetSymbolAddress((void**)&t1,   g_t1);
    float* x1;   cudaGetSymbolAddress((void**)&x1,   g_x1);
    float* x1r;  cudaGetSymbolAddress((void**)&x1r,  g_x1r);
    float* xr;   cudaGetSymbolAddress((void**)&xr,   g_xr);
    float* ffh;  cudaGetSymbolAddress((void**)&ffh,  g_ffh);
    float* wqt;  cudaGetSymbolAddress((void**)&wqt,  g_wqt);
    float* wkt;  cudaGetSymbolAddress((void**)&wkt,  g_wkt);
    float* wvt;  cudaGetSymbolAddress((void**)&wvt,  g_wvt);
    float* wot;  cudaGetSymbolAddress((void**)&wot,  g_wot);
    float* w1t;  cudaGetSymbolAddress((void**)&w1t,  g_w1t);
    float* w2t;  cudaGetSymbolAddress((void**)&w2t,  g_w2t);
    float* attn_fb; cudaGetSymbolAddress((void**)&attn_fb, g_attn_fb);
    float* x_fb;    cudaGetSymbolAddress((void**)&x_fb,    g_x_fb);

    float* out_x;
    float* out_attn;
    const size_t osz = (size_t)out_size;
    if (osz >= X_ELEMS + ATT_ELEMS) {
        out_x = (float*)d_out;
        out_attn = (float*)d_out + X_ELEMS;
    } else if (osz == ATT_ELEMS) {
        out_x = x_fb;
        out_attn = (float*)d_out;
    } else {
        out_x = (float*)d_out;
        out_attn = attn_fb;
    }

    const int M = Bb * Ss;  // 4096
    dim3 blk(256);

    const int smem_projT = 5 * (128 * 20 + 128 * 20) * 4;  // 102,400 B
    const int smem_ctx   = 6 * (128 * 20 + 16 * 68) * 4;   // 87,552 B
    const int smem_fused = 3 * 128 * 68 * 4;                // 104,448 B

    auto* kqkv   = tf32_gemm<128,128,64,32,true, true,false,3,false,true, 5>;
    auto* kproj  = tf32_gemm<128,128,64,32,true, true,false,0,false,false,5>;
    auto* kprojr = tf32_gemm<128,128,64,32,true, true,true, 0,false,true, 5>;
    auto* kctx   = tf32_gemm<128,64,64,16,false,false,false,2,true, true, 6>;
    cudaFuncSetAttribute(kqkv,   cudaFuncAttributeMaxDynamicSharedMemorySize, smem_projT);
    cudaFuncSetAttribute(kproj,  cudaFuncAttributeMaxDynamicSharedMemorySize, smem_projT);
    cudaFuncSetAttribute(kprojr, cudaFuncAttributeMaxDynamicSharedMemorySize, smem_projT);
    cudaFuncSetAttribute(kctx,   cudaFuncAttributeMaxDynamicSharedMemorySize, smem_ctx);
    cudaFuncSetAttribute(fused_scores_softmax,
                         cudaFuncAttributeMaxDynamicSharedMemorySize, smem_fused);

    // round x; round+transpose all 6 weights in ONE launch
    round_kernel<<<(X_ELEMS / 4 + 255) / 256, blk>>>((const float4*)x, (float4*)xr, X_ELEMS / 4);
    {
        RtJobs jb;
        const float* ins[6] = { Wq, Wk, Wv, Wo, W1, W2 };
        float* outs[6]      = { wqt, wkt, wvt, wot, w1t, w2t };
        int Rs[6] = { Dd, Dd, Dd, Dd, Dd, DFFf };
        int Cs[6] = { Dd, Dd, Dd, Dd, DFFf, Dd };
        int base = 0;
        for (int j = 0; j < 6; j++) {
            jb.in[j] = ins[j]; jb.out[j] = outs[j];
            jb.R[j] = Rs[j]; jb.C[j] = Cs[j]; jb.base[j] = base;
            base += (Rs[j] / 32) * (Cs[j] / 32);
        }
        dim3 tblk(32, 8);
        rt_batch_kernel<<<base, tblk>>>(jb);
    }

    // QKV projections (transposed weights [n][k], row stride Dd)
    kqkv<<<dim3(Dd/128, M/128, 3), blk, smem_projT>>>(
        xr, wqt, wkt, wvt, bq, bk, bv, q, k, v, Dd, Dd, Dd, Dd, 1.f);

    // fused scores + softmax (3-stage K pipeline)
    fused_scores_softmax<<<dim3(Ss/32, Bb*Hh), 512, smem_fused>>>(q, k, out_attn);

    // ctx: attn (unrounded -> CVTA) @ V (rounded); 6-stage pipeline
    kctx<<<dim3(1, Ss/128, Bb*Hh), blk, smem_ctx>>>(
        out_attn, v, nullptr, nullptr, nullptr, nullptr, nullptr,
        ctx, nullptr, nullptr, Ss, Ss, Dd, Dd, 1.f);

    // output projection + LN1
    kproj<<<dim3(Dd/128, M/128), blk, smem_projT>>>(
        ctx, wot, nullptr, nullptr, bo, nullptr, nullptr,
        t1, nullptr, nullptr, Dd, Dd, Dd, Dd, 1.f);
    add_ln_kernel<<<M, blk>>>(x, t1, g1, be1, x1, x1r);

    // FFN1: w1t is [DFF][Dd] -> ldb = Dd
    kprojr<<<dim3(DFFf/128, M/128), blk, smem_projT>>>(
        x1r, w1t, nullptr, nullptr, b1, nullptr, nullptr,
        ffh, nullptr, nullptr, Dd, Dd, Dd, DFFf, 1.f);
    // FFN2: w2t is [Dd][DFFf] -> ldb = DFFf
    kproj<<<dim3(Dd/128, M/128), blk, smem_projT>>>(
        ffh, w2t, nullptr, nullptr, b2, nullptr, nullptr,
        t1, nullptr, nullptr, DFFf, DFFf, DFFf, Dd, 1.f);
    add_ln_kernel<<<M, blk>>>(x1, t1, g2, be2, out_x, nullptr);
}

// round 13
// speedup vs baseline: 1.0971x; 1.0031x over previous
#include <cuda_runtime.h>
#include <math_constants.h>
#include <cstdint>

#define Bb 4
#define Ss 1024
#define Dd 1024
#define Hh 16
#define DKk 64
#define DFFf 4096
#define EPSl 1e-5f

#define X_ELEMS   ((size_t)Bb * Ss * Dd)
#define ATT_ELEMS ((size_t)Bb * Hh * Ss * Ss)

// ---------------- scratch ----------------
__device__ float g_q[X_ELEMS];
__device__ float g_k[X_ELEMS];
__device__ float g_v[X_ELEMS];
__device__ float g_ctx[X_ELEMS];
__device__ float g_t1[X_ELEMS];
__device__ float g_x1[X_ELEMS];
__device__ float g_x1r[X_ELEMS];
__device__ float g_xr[X_ELEMS];
__device__ float g_ffh[(size_t)Bb * Ss * DFFf];
__device__ float g_wqt[(size_t)Dd * Dd];
__device__ float g_wkt[(size_t)Dd * Dd];
__device__ float g_wvt[(size_t)Dd * Dd];
__device__ float g_wot[(size_t)Dd * Dd];
__device__ float g_w1t[(size_t)Dd * DFFf];
__device__ float g_w2t[(size_t)Dd * DFFf];
__device__ float g_attn_fb[ATT_ELEMS];
__device__ float g_x_fb[X_ELEMS];

// ---------------- helpers ----------------
__device__ __forceinline__ void cp_async16(void* smem_dst, const void* gsrc) {
    uint32_t s = (uint32_t)__cvta_generic_to_shared(smem_dst);
    asm volatile("cp.async.cg.shared.global [%0], [%1], 16;" :: "r"(s), "l"(gsrc));
}
__device__ __forceinline__ void cp_commit() {
    asm volatile("cp.async.commit_group;");
}
template<int N>
__device__ __forceinline__ void cp_wait() {
    asm volatile("cp.async.wait_group %0;" :: "n"(N));
}
__device__ __forceinline__ uint32_t f2tf(uint32_t x) {
    uint32_t r;
    asm("cvt.rna.tf32.f32 %0, %1;" : "=r"(r) : "f"(__uint_as_float(x)));
    return r;
}
__device__ __forceinline__ float tf32r(float x) {
    return __uint_as_float(f2tf(__float_as_uint(x)));
}
__device__ __forceinline__ void ldsm_x4(uint32_t r[4], uint32_t saddr) {
    asm volatile("ldmatrix.sync.aligned.m8n8.x4.shared.b16 {%0,%1,%2,%3}, [%4];"
                 : "=r"(r[0]), "=r"(r[1]), "=r"(r[2]), "=r"(r[3]) : "r"(saddr));
}
__device__ __forceinline__ void mma_tf32(float c[4], const uint32_t a[4], const uint32_t b[2]) {
    asm volatile(
        "mma.sync.aligned.m16n8k8.row.col.f32.tf32.tf32.f32 "
        "{%0,%1,%2,%3}, {%4,%5,%6,%7}, {%8,%9}, {%0,%1,%2,%3};"
        : "+f"(c[0]), "+f"(c[1]), "+f"(c[2]), "+f"(c[3])
        : "r"(a[0]), "r"(a[1]), "r"(a[2]), "r"(a[3]), "r"(b[0]), "r"(b[1]));
}

// ---------------- round x to tf32 ----------------
__global__ void round_kernel(const float4* __restrict__ in, float4* __restrict__ out, int n4) {
    int i = blockIdx.x * blockDim.x + threadIdx.x;
    if (i >= n4) return;
    float4 v = in[i];
    v.x = tf32r(v.x); v.y = tf32r(v.y); v.z = tf32r(v.z); v.w = tf32r(v.w);
    out[i] = v;
}

// ---------------- batched round + transpose: 6 weights in one launch ----------
struct RtJobs {
    const float* in[6];
    float* out[6];
    int R[6];
    int C[6];
    int base[6];
};
__global__ void rt_batch_kernel(RtJobs jb) {
    __shared__ float tile[32][33];
    const int bx = blockIdx.x;
    int j = 0;
#pragma unroll
    for (int t = 1; t < 6; t++) if (bx >= jb.base[t]) j = t;
    const int tiles_x = jb.C[j] >> 5;
    const int t = bx - jb.base[j];
    const int c0 = (t % tiles_x) * 32;
    const int r0 = (t / tiles_x) * 32;
    const float* in = jb.in[j];
    float* out = jb.out[j];
    const int R = jb.R[j], C = jb.C[j];
    const int tx = threadIdx.x, ty = threadIdx.y;   // 32 x 8
#pragma unroll
    for (int i = 0; i < 4; i++)
        tile[ty + i * 8][tx] = in[(size_t)(r0 + ty + i * 8) * C + c0 + tx];
    __syncthreads();
#pragma unroll
    for (int i = 0; i < 4; i++)
        out[(size_t)(c0 + ty + i * 8) * R + r0 + tx] = tf32r(tile[tx][ty + i * 8]);
}

// ===== fused scores + softmax: 256 thr / 16 q-rows per CTA (2 CTAs/SM) ========
__global__ void __launch_bounds__(256, 2)
fused_scores_softmax(const float* __restrict__ Q, const float* __restrict__ K,
                     float* __restrict__ attn) {
    constexpr int CN = 128;
    constexpr int KST = 68;       // 272B row stride, 16B-aligned
    constexpr int NCH = Ss / CN;  // 8
    constexpr int SK = 3;         // pipeline stages

    extern __shared__ float Ksm[];    // [SK][CN][KST]
    __shared__ float red[16][8];

    const int z = blockIdx.y;
    const int b = z >> 4, h = z & 15;
    const int q0 = blockIdx.x * 16;
    const float* Qb = Q + (size_t)b * Ss * Dd + (size_t)h * DKk;
    const float* Kb = K + (size_t)b * Ss * Dd + (size_t)h * DKk;
    float* Ob = attn + (size_t)z * Ss * Ss;

    const int tid = threadIdx.x;
    const int warp = tid >> 5, lane = tid & 31;
    const int grp = lane >> 2, tig = lane & 3;
    const int wcol = warp;            // 0..7
    const int r0 = q0;

    uint32_t qf[8][4];
#pragma unroll
    for (int ks = 0; ks < 8; ks++) {
        const float* p0 = &Qb[(size_t)(r0 + grp) * Dd + ks * 8 + tig];
        const float* p1 = &Qb[(size_t)(r0 + grp + 8) * Dd + ks * 8 + tig];
        qf[ks][0] = __float_as_uint(p0[0]);
        qf[ks][1] = __float_as_uint(p1[0]);
        qf[ks][2] = __float_as_uint(p0[4]);
        qf[ks][3] = __float_as_uint(p1[4]);
    }

    auto copyK = [&](int stage, int chunk) {
#pragma unroll
        for (int i = 0; i < 8; i++) {     // 128 rows x 16 f4 = 2048 f4 / 256 thr
            int flat = tid + i * 256;
            int r = flat >> 4, c4 = flat & 15;
            cp_async16(&Ksm[stage * CN * KST + r * KST + c4 * 4],
                       &Kb[(size_t)(chunk * CN + r) * Dd + c4 * 4]);
        }
    };

    const uint32_t ksm_base = (uint32_t)__cvta_generic_to_shared(Ksm);
    const int kf_off = (wcol * 16 + ((lane >> 4) << 3) + (lane & 7)) * KST
                     + (((lane >> 3) & 1) << 2);

    float acc[NCH][2][4];
#pragma unroll
    for (int c = 0; c < NCH; c++)
#pragma unroll
        for (int j = 0; j < 2; j++)
#pragma unroll
            for (int q = 0; q < 4; q++) acc[c][j][q] = 0.f;

    int fetch = 0;
    for (; fetch < SK - 1; fetch++) { copyK(fetch, fetch); cp_commit(); }

    for (int c = 0; c < NCH; c++) {
        cp_wait<SK - 2>();
        __syncthreads();
        if (fetch < NCH) { copyK(fetch % SK, fetch); fetch++; }
        cp_commit();
        const uint32_t cb = ksm_base + 4u * ((c % SK) * CN * KST + kf_off);
#pragma unroll
        for (int ks = 0; ks < 8; ks++) {
            uint32_t r[4];
            ldsm_x4(r, cb + 4u * (ks * 8));
            uint32_t bf0[2] = { r[0], r[1] };
            uint32_t bf1[2] = { r[2], r[3] };
            mma_tf32(acc[c][0], qf[ks], bf0);
            mma_tf32(acc[c][1], qf[ks], bf1);
        }
    }
    __syncthreads();

    float m0 = -CUDART_INF_F, m1 = -CUDART_INF_F;
#pragma unroll
    for (int c = 0; c < NCH; c++)
#pragma unroll
        for (int j = 0; j < 2; j++) {
            acc[c][j][0] *= 0.125f; acc[c][j][1] *= 0.125f;
            acc[c][j][2] *= 0.125f; acc[c][j][3] *= 0.125f;
            m0 = fmaxf(m0, fmaxf(acc[c][j][0], acc[c][j][1]));
            m1 = fmaxf(m1, fmaxf(acc[c][j][2], acc[c][j][3]));
        }
    m0 = fmaxf(m0, __shfl_xor_sync(~0u, m0, 1));
    m0 = fmaxf(m0, __shfl_xor_sync(~0u, m0, 2));
    m1 = fmaxf(m1, __shfl_xor_sync(~0u, m1, 1));
    m1 = fmaxf(m1, __shfl_xor_sync(~0u, m1, 2));
    if (tig == 0) {
        red[grp][wcol] = m0;
        red[grp + 8][wcol] = m1;
    }
    __syncthreads();
    m0 = red[grp][0];
    m1 = red[grp + 8][0];
#pragma unroll
    for (int w = 1; w < 8; w++) {
        m0 = fmaxf(m0, red[grp][w]);
        m1 = fmaxf(m1, red[grp + 8][w]);
    }
    __syncthreads();

    float s0 = 0.f, s1 = 0.f;
#pragma unroll
    for (int c = 0; c < NCH; c++)
#pragma unroll
        for (int j = 0; j < 2; j++) {
            acc[c][j][0] = __expf(acc[c][j][0] - m0);
            acc[c][j][1] = __expf(acc[c][j][1] - m0);
            acc[c][j][2] = __expf(acc[c][j][2] - m1);
            acc[c][j][3] = __expf(acc[c][j][3] - m1);
            s0 += acc[c][j][0] + acc[c][j][1];
            s1 += acc[c][j][2] + acc[c][j][3];
        }
    s0 += __shfl_xor_sync(~0u, s0, 1);
    s0 += __shfl_xor_sync(~0u, s0, 2);
    s1 += __shfl_xor_sync(~0u, s1, 1);
    s1 += __shfl_xor_sync(~0u, s1, 2);
    if (tig == 0) {
        red[grp][wcol] = s0;
        red[grp + 8][wcol] = s1;
    }
    __syncthreads();
    s0 = 0.f; s1 = 0.f;
#pragma unroll
    for (int w = 0; w < 8; w++) {
        s0 += red[grp][w];
        s1 += red[grp + 8][w];
    }
    const float i0 = 1.f / s0, i1 = 1.f / s1;

    float* O0 = &Ob[(size_t)(r0 + grp) * Ss];
    float* O1 = &Ob[(size_t)(r0 + grp + 8) * Ss];
#pragma unroll
    for (int c = 0; c < NCH; c++)
#pragma unroll
        for (int j = 0; j < 2; j++) {
            int col = c * 128 + wcol * 16 + j * 8 + tig * 2;
            *(float2*)&O0[col] = make_float2(acc[c][j][0] * i0, acc[c][j][1] * i0);
            *(float2*)&O1[col] = make_float2(acc[c][j][2] * i1, acc[c][j][3] * i1);
        }
}

// MODE: 0 = plain GEMM. 2 = ctx. 3 = QKV batched.
// TRANSB: B stored [n][k] (pre-transposed weights) -> ldsm fragment loads.
// CVTA: rna-round A fragments. ROUT: round epilogue output. STAGES: cp.async depth.
template<int BM, int BN, int WM, int WN, bool TRANSB, bool BIAS, bool RELU,
         int MODE, bool CVTA, bool ROUT, int STAGES>
__global__ void __launch_bounds__(256)
tf32_gemm(const float* __restrict__ A,
          const float* __restrict__ B0, const float* __restrict__ B1p, const float* __restrict__ B2p,
          const float* __restrict__ bias0, const float* __restrict__ bias1, const float* __restrict__ bias2,
          float* __restrict__ C0, float* __restrict__ C1p, float* __restrict__ C2p,
          int K, int lda, int ldb, int ldc, float scale) {
    constexpr int BK = 16;
    constexpr int WCOLS = BN / WN;
    constexpr int AM = WM / 16;
    constexpr int BNT = WN / 8;
    constexpr int ASTRIDE = BK + 4;
    constexpr int BSTRIDE = TRANSB ? (BK + 4) : (BN + 4);
    constexpr int SA = BM * ASTRIDE;
    constexpr int SB = TRANSB ? (BN * ASTRIDE) : (BK * (BN + 4));
    constexpr int LDA_V = BM * BK / (4 * 256);
    constexpr int LDB_V = (TRANSB ? BN * BK : BK * BN) / (4 * 256);

    extern __shared__ float smem[];
    float* As = smem;
    float* Bs = smem + STAGES * SA;

    const int tid = threadIdx.x;
    const int warp = tid >> 5, lane = tid & 31;
    const int grp = lane >> 2, tig = lane & 3;
    const int wm = (warp / WCOLS) * WM;
    const int wn = (warp % WCOLS) * WN;
    const int row0 = blockIdx.y * BM;
    const int col0 = blockIdx.x * BN;
    const int z = blockIdx.z;

    const float* Bsel = B0;
    const float* biasSel = bias0;
    float* Csel = C0;
    if (MODE == 3) {
        if (z == 1) { Bsel = B1p; biasSel = bias1; Csel = C1p; }
        else if (z == 2) { Bsel = B2p; biasSel = bias2; Csel = C2p; }
    }

    size_t offA = 0, offB = 0, offC = 0;
    if (MODE == 2) {
        size_t ho = (size_t)(z >> 4) * Ss * Dd + (size_t)(z & 15) * DKk;
        offA = (size_t)z * Ss * Ss; offB = ho; offC = ho;
    }
    const float* Ag = A + offA;
    const float* Bg = Bsel + offB;
    float* Cg = Csel + offC;

    auto copyA = [&](int stage, int k0) {
#pragma unroll
        for (int i = 0; i < LDA_V; i++) {
            int flat = tid + i * 256;
            int r = flat >> 2, c4 = flat & 3;
            cp_async16(&As[stage * SA + r * ASTRIDE + c4 * 4],
                       &Ag[(size_t)(row0 + r) * lda + k0 + c4 * 4]);
        }
    };
    auto copyB = [&](int stage, int k0) {
#pragma unroll
        for (int i = 0; i < LDB_V; i++) {
            int flat = tid + i * 256;
            if (TRANSB) {
                int n = flat >> 2, c4 = flat & 3;
                cp_async16(&Bs[stage * SB + n * BSTRIDE + c4 * 4],
                           &Bg[(size_t)(col0 + n) * ldb + k0 + c4 * 4]);
            } else {
                constexpr int C4 = BN / 4;
                int r = flat / C4, c4 = flat % C4;
                cp_async16(&Bs[stage * SB + r * BSTRIDE + c4 * 4],
                           &Bg[(size_t)(k0 + r) * ldb + col0 + c4 * 4]);
            }
        }
    };

    const uint32_t as_base = (uint32_t)__cvta_generic_to_shared(As);
    const uint32_t bs_base = (uint32_t)__cvta_generic_to_shared(Bs);
    const int a_thr_off = (wm + ((lane >> 3) & 1) * 8 + (lane & 7)) * ASTRIDE
                        + ((lane >> 4) ? 4 : 0);
    const int b4_off = TRANSB
        ? (wn + ((lane >> 4) << 3) + (lane & 7)) * BSTRIDE + (((lane >> 3) & 1) << 2)
        : 0;

    float acc[AM][BNT][4];
#pragma unroll
    for (int i = 0; i < AM; i++)
#pragma unroll
        for (int j = 0; j < BNT; j++)
#pragma unroll
            for (int q = 0; q < 4; q++) acc[i][j][q] = 0.f;

    const int KT = K / BK;
    int fetch = 0;
    for (; fetch < STAGES - 1; fetch++) {
        copyA(fetch, fetch * BK);
        copyB(fetch, fetch * BK);
        cp_commit();
    }

    for (int kt = 0; kt < KT; kt++) {
        cp_wait<STAGES - 2>();
        __syncthreads();
        if (fetch < KT) {
            copyA(fetch % STAGES, fetch * BK);
            copyB(fetch % STAGES, fetch * BK);
            fetch++;
        }
        cp_commit();

        const int buf = kt % STAGES;
        const float* Bsb = &Bs[buf * SB];
#pragma unroll
        for (int ks = 0; ks < BK; ks += 8) {
            uint32_t af[AM][4];
            uint32_t bf[BNT][2];
#pragma unroll
            for (int i = 0; i < AM; i++) {
                uint32_t addr = as_base + 4u * (buf * SA + a_thr_off + i * 16 * ASTRIDE + ks);
                ldsm_x4(af[i], addr);
                if (CVTA) {
                    af[i][0] = f2tf(af[i][0]); af[i][1] = f2tf(af[i][1]);
                    af[i][2] = f2tf(af[i][2]); af[i][3] = f2tf(af[i][3]);
                }
            }
            if (TRANSB) {
#pragma unroll
                for (int j = 0; j < BNT; j += 2) {
                    uint32_t r[4];
                    ldsm_x4(r, bs_base + 4u * (buf * SB + b4_off + j * 8 * BSTRIDE + ks));
                    bf[j][0] = r[0]; bf[j][1] = r[1];
                    bf[j + 1][0] = r[2]; bf[j + 1][1] = r[3];
                }
            } else {
#pragma unroll
                for (int j = 0; j < BNT; j++) {
                    int n = wn + j * 8 + grp;
                    bf[j][0] = __float_as_uint(Bsb[(ks + tig) * BSTRIDE + n]);
                    bf[j][1] = __float_as_uint(Bsb[(ks + tig + 4) * BSTRIDE + n]);
                }
            }
#pragma unroll
            for (int i = 0; i < AM; i++)
#pragma unroll
                for (int j = 0; j < BNT; j++)
                    mma_tf32(acc[i][j], af[i], bf[j]);
        }
    }

#pragma unroll
    for (int i = 0; i < AM; i++) {
        int r1 = row0 + wm + i * 16 + grp;
        int r2 = r1 + 8;
#pragma unroll
        for (int j = 0; j < BNT; j++) {
            int cc = col0 + wn + j * 8 + tig * 2;
            float b0v = 0.f, b1v = 0.f;
            if (BIAS) { b0v = biasSel[cc]; b1v = biasSel[cc + 1]; }
            float v0 = acc[i][j][0] * scale + b0v;
            float v1 = acc[i][j][1] * scale + b1v;
            float v2 = acc[i][j][2] * scale + b0v;
            float v3 = acc[i][j][3] * scale + b1v;
            if (RELU) {
                v0 = fmaxf(v0, 0.f); v1 = fmaxf(v1, 0.f);
                v2 = fmaxf(v2, 0.f); v3 = fmaxf(v3, 0.f);
            }
            if (ROUT) {
                v0 = tf32r(v0); v1 = tf32r(v1); v2 = tf32r(v2); v3 = tf32r(v3);
            }
            *(float2*)&Cg[(size_t)r1 * ldc + cc] = make_float2(v0, v1);
            *(float2*)&Cg[(size_t)r2 * ldc + cc] = make_float2(v2, v3);
        }
    }
}

// ---------------- residual add + layernorm (dual output) ----------------------
__global__ void add_ln_kernel(const float* __restrict__ a,
                              const float* __restrict__ bres,
                              const float* __restrict__ g,
                              const float* __restrict__ be,
                              float* __restrict__ out,
                              float* __restrict__ out_r) {
    const size_t row = blockIdx.x;
    const float4* pa = (const float4*)(a + row * Dd);
    const float4* pb = (const float4*)(bres + row * Dd);
    float4* po = (float4*)(out + row * Dd);
    const int tid = threadIdx.x;  // 256
    __shared__ float red[8];
    float4 va = pa[tid], vb = pb[tid];
    float4 v = make_float4(va.x + vb.x, va.y + vb.y, va.z + vb.z, va.w + vb.w);
    float s = v.x + v.y + v.z + v.w;
#pragma unroll
    for (int o = 16; o > 0; o >>= 1) s += __shfl_xor_sync(~0u, s, o);
    if ((tid & 31) == 0) red[tid >> 5] = s;
    __syncthreads();
    s = red[tid & 7];
#pragma unroll
    for (int o = 4; o > 0; o >>= 1) s += __shfl_xor_sync(~0u, s, o);
    const float mu = s * (1.f / Dd);
    float q = (v.x - mu) * (v.x - mu) + (v.y - mu) * (v.y - mu)
            + (v.z - mu) * (v.z - mu) + (v.w - mu) * (v.w - mu);
#pragma unroll
    for (int o = 16; o > 0; o >>= 1) q += __shfl_xor_sync(~0u, q, o);
    __syncthreads();
    if ((tid & 31) == 0) red[tid >> 5] = q;
    __syncthreads();
    q = red[tid & 7];
#pragma unroll
    for (int o = 4; o > 0; o >>= 1) q += __shfl_xor_sync(~0u, q, o);
    const float inv = rsqrtf(q * (1.f / Dd) + EPSl);
    float4 vg = ((const float4*)g)[tid], vbe = ((const float4*)be)[tid];
    float4 r = make_float4((v.x - mu) * inv * vg.x + vbe.x,
                           (v.y - mu) * inv * vg.y + vbe.y,
                           (v.z - mu) * inv * vg.z + vbe.z,
                           (v.w - mu) * inv * vg.w + vbe.w);
    po[tid] = r;
    if (out_r) {
        float4 rr = make_float4(tf32r(r.x), tf32r(r.y), tf32r(r.z), tf32r(r.w));
        ((float4*)(out_r + row * Dd))[tid] = rr;
    }
}

// ---------------- launch -------------------------------------------------------
extern "C" void kernel_launch(void* const* d_in, const int* in_sizes, int n_in,
                              void* d_out, int out_size) {
    const float* x  = (const float*)d_in[0];
    const float* Wq = (const float*)d_in[1];
    const float* bq = (const float*)d_in[2];
    const float* Wk = (const float*)d_in[3];
    const float* bk = (const float*)d_in[4];
    const float* Wv = (const float*)d_in[5];
    const float* bv = (const float*)d_in[6];
    const float* Wo = (const float*)d_in[7];
    const float* bo = (const float*)d_in[8];
    const float* W1 = (const float*)d_in[9];
    const float* b1 = (const float*)d_in[10];
    const float* W2 = (const float*)d_in[11];
    const float* b2 = (const float*)d_in[12];
    const float* g1 = (const float*)d_in[13];
    const float* be1 = (const float*)d_in[14];
    const float* g2 = (const float*)d_in[15];
    const float* be2 = (const float*)d_in[16];

    float* q;    cudaGetSymbolAddress((void**)&q,    g_q);
    float* k;    cudaGetSymbolAddress((void**)&k,    g_k);
    float* v;    cudaGetSymbolAddress((void**)&v,    g_v);
    float* ctx;  cudaGetSymbolAddress((void**)&ctx,  g_ctx);
    float* t1;   cudaGetSymbolAddress((void**)&t1,   g_t1);
    float* x1;   cudaGetSymbolAddress((void**)&x1,   g_x1);
    float* x1r;  cudaGetSymbolAddress((void**)&x1r,  g_x1r);
    float* xr;   cudaGetSymbolAddress((void**)&xr,   g_xr);
    float* ffh;  cudaGetSymbolAddress((void**)&ffh,  g_ffh);
    float* wqt;  cudaGetSymbolAddress((void**)&wqt,  g_wqt);
    float* wkt;  cudaGetSymbolAddress((void**)&wkt,  g_wkt);
    float* wvt;  cudaGetSymbolAddress((void**)&wvt,  g_wvt);
    float* wot;  cudaGetSymbolAddress((void**)&wot,  g_wot);
    float* w1t;  cudaGetSymbolAddress((void**)&w1t,  g_w1t);
    float* w2t;  cudaGetSymbolAddress((void**)&w2t,  g_w2t);
    float* attn_fb; cudaGetSymbolAddress((void**)&attn_fb, g_attn_fb);
    float* x_fb;    cudaGetSymbolAddress((void**)&x_fb,    g_x_fb);

    float* out_x;
    float* out_attn;
    const size_t osz = (size_t)out_size;
    if (osz >= X_ELEMS + ATT_ELEMS) {
        out_x = (float*)d_out;
        out_attn = (float*)d_out + X_ELEMS;
    } else if (osz == ATT_ELEMS) {
        out_x = x_fb;
        out_attn = (float*)d_out;
    } else {
        out_x = (float*)d_out;
        out_attn = attn_fb;
    }

    const int M = Bb * Ss;  // 4096
    dim3 blk(256);

    const int smem_projT = 5 * (128 * 20 + 128 * 20) * 4;  // 102,400 B
    const int smem_ctx   = 6 * (128 * 20 + 16 * 68) * 4;   // 87,552 B
    const int smem_fused = 3 * 128 * 68 * 4;                // 104,448 B

    auto* kqkv   = tf32_gemm<128,128,64,32,true, true,false,3,false,true, 5>;
    auto* kproj  = tf32_gemm<128,128,64,32,true, true,false,0,false,false,5>;
    auto* kprojr = tf32_gemm<128,128,64,32,true, true,true, 0,false,true, 5>;
    auto* kctx   = tf32_gemm<128,64,64,16,false,false,false,2,true, true, 6>;
    cudaFuncSetAttribute(kqkv,   cudaFuncAttributeMaxDynamicSharedMemorySize, smem_projT);
    cudaFuncSetAttribute(kproj,  cudaFuncAttributeMaxDynamicSharedMemorySize, smem_projT);
    cudaFuncSetAttribute(kprojr, cudaFuncAttributeMaxDynamicSharedMemorySize, smem_projT);
    cudaFuncSetAttribute(kctx,   cudaFuncAttributeMaxDynamicSharedMemorySize, smem_ctx);
    cudaFuncSetAttribute(fused_scores_softmax,
                         cudaFuncAttributeMaxDynamicSharedMemorySize, smem_fused);

    // round x; round+transpose all 6 weights in ONE launch
    round_kernel<<<(X_ELEMS / 4 + 255) / 256, blk>>>((const float4*)x, (float4*)xr, X_ELEMS / 4);
    {
        RtJobs jb;
        const float* ins[6] = { Wq, Wk, Wv, Wo, W1, W2 };
        float* outs[6]      = { wqt, wkt, wvt, wot, w1t, w2t };
        int Rs[6] = { Dd, Dd, Dd, Dd, Dd, DFFf };
        int Cs[6] = { Dd, Dd, Dd, Dd, DFFf, Dd };
        int base = 0;
        for (int j = 0; j < 6; j++) {
            jb.in[j] = ins[j]; jb.out[j] = outs[j];
            jb.R[j] = Rs[j]; jb.C[j] = Cs[j]; jb.base[j] = base;
            base += (Rs[j] / 32) * (Cs[j] / 32);
        }
        dim3 tblk(32, 8);
        rt_batch_kernel<<<base, tblk>>>(jb);
    }

    // QKV projections (transposed weights [n][k], row stride Dd)
    kqkv<<<dim3(Dd/128, M/128, 3), blk, smem_projT>>>(
        xr, wqt, wkt, wvt, bq, bk, bv, q, k, v, Dd, Dd, Dd, Dd, 1.f);

    // fused scores + softmax: 16 q-rows / 256 threads per CTA, 2 CTAs/SM
    fused_scores_softmax<<<dim3(Ss/16, Bb*Hh), 256, smem_fused>>>(q, k, out_attn);

    // ctx: attn (unrounded -> CVTA) @ V (rounded); 6-stage pipeline
    kctx<<<dim3(1, Ss/128, Bb*Hh), blk, smem_ctx>>>(
        out_attn, v, nullptr, nullptr, nullptr, nullptr, nullptr,
        ctx, nullptr, nullptr, Ss, Ss, Dd, Dd, 1.f);

    // output projection + LN1
    kproj<<<dim3(Dd/128, M/128), blk, smem_projT>>>(
        ctx, wot, nullptr, nullptr, bo, nullptr, nullptr,
        t1, nullptr, nullptr, Dd, Dd, Dd, Dd, 1.f);
    add_ln_kernel<<<M, blk>>>(x, t1, g1, be1, x1, x1r);

    // FFN1: w1t is [DFF][Dd] -> ldb = Dd
    kprojr<<<dim3(DFFf/128, M/128), blk, smem_projT>>>(
        x1r, w1t, nullptr, nullptr, b1, nullptr, nullptr,
        ffh, nullptr, nullptr, Dd, Dd, Dd, DFFf, 1.f);
    // FFN2: w2t is [Dd][DFFf] -> ldb = DFFf
    kproj<<<dim3(Dd/128, M/128), blk, smem_projT>>>(
        ffh, w2t, nullptr, nullptr, b2, nullptr, nullptr,
        t1, nullptr, nullptr, DFFf, DFFf, DFFf, Dd, 1.f);
    add_ln_kernel<<<M, blk>>>(x1, t1, g2, be2, out_x, nullptr);
}

// round 14
// speedup vs baseline: 1.2037x; 1.0972x over previous
#include <cuda_runtime.h>
#include <math_constants.h>
#include <cstdint>

#define Bb 4
#define Ss 1024
#define Dd 1024
#define Hh 16
#define DKk 64
#define DFFf 4096
#define EPSl 1e-5f

#define X_ELEMS   ((size_t)Bb * Ss * Dd)
#define ATT_ELEMS ((size_t)Bb * Hh * Ss * Ss)

// ---------------- scratch ----------------
__device__ float g_q[X_ELEMS];
__device__ float g_k[X_ELEMS];
__device__ float g_v[X_ELEMS];
__device__ float g_ctx[X_ELEMS];
__device__ float g_t1[X_ELEMS];
__device__ float g_x1[X_ELEMS];
__device__ float g_x1r[X_ELEMS];
__device__ float g_xr[X_ELEMS];
__device__ float g_ffh[(size_t)Bb * Ss * DFFf];
__device__ float g_wqt[(size_t)Dd * Dd];
__device__ float g_wkt[(size_t)Dd * Dd];
__device__ float g_wvt[(size_t)Dd * Dd];
__device__ float g_wot[(size_t)Dd * Dd];
__device__ float g_w1t[(size_t)Dd * DFFf];
__device__ float g_w2t[(size_t)Dd * DFFf];
__device__ float g_attn_fb[ATT_ELEMS];
__device__ float g_x_fb[X_ELEMS];

// ---------------- helpers ----------------
__device__ __forceinline__ void cp_async16(void* smem_dst, const void* gsrc) {
    uint32_t s = (uint32_t)__cvta_generic_to_shared(smem_dst);
    asm volatile("cp.async.cg.shared.global [%0], [%1], 16;" :: "r"(s), "l"(gsrc));
}
__device__ __forceinline__ void cp_commit() {
    asm volatile("cp.async.commit_group;");
}
template<int N>
__device__ __forceinline__ void cp_wait() {
    asm volatile("cp.async.wait_group %0;" :: "n"(N));
}
__device__ __forceinline__ uint32_t f2tf(uint32_t x) {
    uint32_t r;
    asm("cvt.rna.tf32.f32 %0, %1;" : "=r"(r) : "f"(__uint_as_float(x)));
    return r;
}
__device__ __forceinline__ float tf32r(float x) {
    return __uint_as_float(f2tf(__float_as_uint(x)));
}
__device__ __forceinline__ void ldsm_x4(uint32_t r[4], uint32_t saddr) {
    asm volatile("ldmatrix.sync.aligned.m8n8.x4.shared.b16 {%0,%1,%2,%3}, [%4];"
                 : "=r"(r[0]), "=r"(r[1]), "=r"(r[2]), "=r"(r[3]) : "r"(saddr));
}
__device__ __forceinline__ void mma_tf32(float c[4], const uint32_t a[4], const uint32_t b[2]) {
    asm volatile(
        "mma.sync.aligned.m16n8k8.row.col.f32.tf32.tf32.f32 "
        "{%0,%1,%2,%3}, {%4,%5,%6,%7}, {%8,%9}, {%0,%1,%2,%3};"
        : "+f"(c[0]), "+f"(c[1]), "+f"(c[2]), "+f"(c[3])
        : "r"(a[0]), "r"(a[1]), "r"(a[2]), "r"(a[3]), "r"(b[0]), "r"(b[1]));
}

// ---------------- round x to tf32 ----------------
__global__ void round_kernel(const float4* __restrict__ in, float4* __restrict__ out, int n4) {
    int i = blockIdx.x * blockDim.x + threadIdx.x;
    if (i >= n4) return;
    float4 v = in[i];
    v.x = tf32r(v.x); v.y = tf32r(v.y); v.z = tf32r(v.z); v.w = tf32r(v.w);
    out[i] = v;
}

// ---------------- batched round + transpose: 6 weights in one launch ----------
struct RtJobs {
    const float* in[6];
    float* out[6];
    int R[6];
    int C[6];
    int base[6];
};
__global__ void rt_batch_kernel(RtJobs jb) {
    __shared__ float tile[32][33];
    const int bx = blockIdx.x;
    int j = 0;
#pragma unroll
    for (int t = 1; t < 6; t++) if (bx >= jb.base[t]) j = t;
    const int tiles_x = jb.C[j] >> 5;
    const int t = bx - jb.base[j];
    const int c0 = (t % tiles_x) * 32;
    const int r0 = (t / tiles_x) * 32;
    const float* in = jb.in[j];
    float* out = jb.out[j];
    const int R = jb.R[j], C = jb.C[j];
    const int tx = threadIdx.x, ty = threadIdx.y;   // 32 x 8
#pragma unroll
    for (int i = 0; i < 4; i++)
        tile[ty + i * 8][tx] = in[(size_t)(r0 + ty + i * 8) * C + c0 + tx];
    __syncthreads();
#pragma unroll
    for (int i = 0; i < 4; i++)
        out[(size_t)(c0 + ty + i * 8) * R + r0 + tx] = tf32r(tile[tx][ty + i * 8]);
}

// ===== fused scores + softmax: 256 thr / 16 q-rows per CTA ====================
__global__ void __launch_bounds__(256, 2)
fused_scores_softmax(const float* __restrict__ Q, const float* __restrict__ K,
                     float* __restrict__ attn) {
    constexpr int CN = 128;
    constexpr int KST = 68;
    constexpr int NCH = Ss / CN;  // 8
    constexpr int SK = 3;

    extern __shared__ float Ksm[];    // [SK][CN][KST]
    __shared__ float red[16][8];

    const int z = blockIdx.y;
    const int b = z >> 4, h = z & 15;
    const int q0 = blockIdx.x * 16;
    const float* Qb = Q + (size_t)b * Ss * Dd + (size_t)h * DKk;
    const float* Kb = K + (size_t)b * Ss * Dd + (size_t)h * DKk;
    float* Ob = attn + (size_t)z * Ss * Ss;

    const int tid = threadIdx.x;
    const int warp = tid >> 5, lane = tid & 31;
    const int grp = lane >> 2, tig = lane & 3;
    const int wcol = warp;
    const int r0 = q0;

    uint32_t qf[8][4];
#pragma unroll
    for (int ks = 0; ks < 8; ks++) {
        const float* p0 = &Qb[(size_t)(r0 + grp) * Dd + ks * 8 + tig];
        const float* p1 = &Qb[(size_t)(r0 + grp + 8) * Dd + ks * 8 + tig];
        qf[ks][0] = __float_as_uint(p0[0]);
        qf[ks][1] = __float_as_uint(p1[0]);
        qf[ks][2] = __float_as_uint(p0[4]);
        qf[ks][3] = __float_as_uint(p1[4]);
    }

    auto copyK = [&](int stage, int chunk) {
#pragma unroll
        for (int i = 0; i < 8; i++) {
            int flat = tid + i * 256;
            int r = flat >> 4, c4 = flat & 15;
            cp_async16(&Ksm[stage * CN * KST + r * KST + c4 * 4],
                       &Kb[(size_t)(chunk * CN + r) * Dd + c4 * 4]);
        }
    };

    const uint32_t ksm_base = (uint32_t)__cvta_generic_to_shared(Ksm);
    const int kf_off = (wcol * 16 + ((lane >> 4) << 3) + (lane & 7)) * KST
                     + (((lane >> 3) & 1) << 2);

    float acc[NCH][2][4];
#pragma unroll
    for (int c = 0; c < NCH; c++)
#pragma unroll
        for (int j = 0; j < 2; j++)
#pragma unroll
            for (int q = 0; q < 4; q++) acc[c][j][q] = 0.f;

    int fetch = 0;
    for (; fetch < SK - 1; fetch++) { copyK(fetch, fetch); cp_commit(); }

    for (int c = 0; c < NCH; c++) {
        cp_wait<SK - 2>();
        __syncthreads();
        if (fetch < NCH) { copyK(fetch % SK, fetch); fetch++; }
        cp_commit();
        const uint32_t cb = ksm_base + 4u * ((c % SK) * CN * KST + kf_off);
#pragma unroll
        for (int ks = 0; ks < 8; ks++) {
            uint32_t r[4];
            ldsm_x4(r, cb + 4u * (ks * 8));
            uint32_t bf0[2] = { r[0], r[1] };
            uint32_t bf1[2] = { r[2], r[3] };
            mma_tf32(acc[c][0], qf[ks], bf0);
            mma_tf32(acc[c][1], qf[ks], bf1);
        }
    }
    __syncthreads();

    float m0 = -CUDART_INF_F, m1 = -CUDART_INF_F;
#pragma unroll
    for (int c = 0; c < NCH; c++)
#pragma unroll
        for (int j = 0; j < 2; j++) {
            acc[c][j][0] *= 0.125f; acc[c][j][1] *= 0.125f;
            acc[c][j][2] *= 0.125f; acc[c][j][3] *= 0.125f;
            m0 = fmaxf(m0, fmaxf(acc[c][j][0], acc[c][j][1]));
            m1 = fmaxf(m1, fmaxf(acc[c][j][2], acc[c][j][3]));
        }
    m0 = fmaxf(m0, __shfl_xor_sync(~0u, m0, 1));
    m0 = fmaxf(m0, __shfl_xor_sync(~0u, m0, 2));
    m1 = fmaxf(m1, __shfl_xor_sync(~0u, m1, 1));
    m1 = fmaxf(m1, __shfl_xor_sync(~0u, m1, 2));
    if (tig == 0) {
        red[grp][wcol] = m0;
        red[grp + 8][wcol] = m1;
    }
    __syncthreads();
    m0 = red[grp][0];
    m1 = red[grp + 8][0];
#pragma unroll
    for (int w = 1; w < 8; w++) {
        m0 = fmaxf(m0, red[grp][w]);
        m1 = fmaxf(m1, red[grp + 8][w]);
    }
    __syncthreads();

    float s0 = 0.f, s1 = 0.f;
#pragma unroll
    for (int c = 0; c < NCH; c++)
#pragma unroll
        for (int j = 0; j < 2; j++) {
            acc[c][j][0] = __expf(acc[c][j][0] - m0);
            acc[c][j][1] = __expf(acc[c][j][1] - m0);
            acc[c][j][2] = __expf(acc[c][j][2] - m1);
            acc[c][j][3] = __expf(acc[c][j][3] - m1);
            s0 += acc[c][j][0] + acc[c][j][1];
            s1 += acc[c][j][2] + acc[c][j][3];
        }
    s0 += __shfl_xor_sync(~0u, s0, 1);
    s0 += __shfl_xor_sync(~0u, s0, 2);
    s1 += __shfl_xor_sync(~0u, s1, 1);
    s1 += __shfl_xor_sync(~0u, s1, 2);
    if (tig == 0) {
        red[grp][wcol] = s0;
        red[grp + 8][wcol] = s1;
    }
    __syncthreads();
    s0 = 0.f; s1 = 0.f;
#pragma unroll
    for (int w = 0; w < 8; w++) {
        s0 += red[grp][w];
        s1 += red[grp + 8][w];
    }
    const float i0 = 1.f / s0, i1 = 1.f / s1;

    float* O0 = &Ob[(size_t)(r0 + grp) * Ss];
    float* O1 = &Ob[(size_t)(r0 + grp + 8) * Ss];
#pragma unroll
    for (int c = 0; c < NCH; c++)
#pragma unroll
        for (int j = 0; j < 2; j++) {
            int col = c * 128 + wcol * 16 + j * 8 + tig * 2;
            *(float2*)&O0[col] = make_float2(acc[c][j][0] * i0, acc[c][j][1] * i0);
            *(float2*)&O1[col] = make_float2(acc[c][j][2] * i1, acc[c][j][3] * i1);
        }
}

// MODE: 0 = plain GEMM. 2 = ctx. 3 = QKV batched.
// TRANSB: B stored [n][k]. CVTA: round A fragments. ROUT: round output.
// STAGES: cp.async depth. BK: k-chunk per stage (multiple of 8).
template<int BM, int BN, int WM, int WN, bool TRANSB, bool BIAS, bool RELU,
         int MODE, bool CVTA, bool ROUT, int STAGES, int BK>
__global__ void __launch_bounds__(256)
tf32_gemm(const float* __restrict__ A,
          const float* __restrict__ B0, const float* __restrict__ B1p, const float* __restrict__ B2p,
          const float* __restrict__ bias0, const float* __restrict__ bias1, const float* __restrict__ bias2,
          float* __restrict__ C0, float* __restrict__ C1p, float* __restrict__ C2p,
          int K, int lda, int ldb, int ldc, float scale) {
    constexpr int WCOLS = BN / WN;
    constexpr int AM = WM / 16;
    constexpr int BNT = WN / 8;
    constexpr int ASTRIDE = BK + 4;
    constexpr int BSTRIDE = TRANSB ? (BK + 4) : (BN + 4);
    constexpr int SA = BM * ASTRIDE;
    constexpr int SB = TRANSB ? (BN * ASTRIDE) : (BK * (BN + 4));
    constexpr int LDA_V = BM * BK / (4 * 256);
    constexpr int LDB_V = (TRANSB ? BN * BK : BK * BN) / (4 * 256);
    constexpr int F4R = BK / 4;   // float4 per k-row

    extern __shared__ float smem[];
    float* As = smem;
    float* Bs = smem + STAGES * SA;

    const int tid = threadIdx.x;
    const int warp = tid >> 5, lane = tid & 31;
    const int grp = lane >> 2, tig = lane & 3;
    const int wm = (warp / WCOLS) * WM;
    const int wn = (warp % WCOLS) * WN;
    const int row0 = blockIdx.y * BM;
    const int col0 = blockIdx.x * BN;
    const int z = blockIdx.z;

    const float* Bsel = B0;
    const float* biasSel = bias0;
    float* Csel = C0;
    if (MODE == 3) {
        if (z == 1) { Bsel = B1p; biasSel = bias1; Csel = C1p; }
        else if (z == 2) { Bsel = B2p; biasSel = bias2; Csel = C2p; }
    }

    size_t offA = 0, offB = 0, offC = 0;
    if (MODE == 2) {
        size_t ho = (size_t)(z >> 4) * Ss * Dd + (size_t)(z & 15) * DKk;
        offA = (size_t)z * Ss * Ss; offB = ho; offC = ho;
    }
    const float* Ag = A + offA;
    const float* Bg = Bsel + offB;
    float* Cg = Csel + offC;

    auto copyA = [&](int stage, int k0) {
#pragma unroll
        for (int i = 0; i < LDA_V; i++) {
            int flat = tid + i * 256;
            int r = flat / F4R, c4 = flat % F4R;
            cp_async16(&As[stage * SA + r * ASTRIDE + c4 * 4],
                       &Ag[(size_t)(row0 + r) * lda + k0 + c4 * 4]);
        }
    };
    auto copyB = [&](int stage, int k0) {
#pragma unroll
        for (int i = 0; i < LDB_V; i++) {
            int flat = tid + i * 256;
            if (TRANSB) {
                int n = flat / F4R, c4 = flat % F4R;
                cp_async16(&Bs[stage * SB + n * BSTRIDE + c4 * 4],
                           &Bg[(size_t)(col0 + n) * ldb + k0 + c4 * 4]);
            } else {
                constexpr int C4 = BN / 4;
                int r = flat / C4, c4 = flat % C4;
                cp_async16(&Bs[stage * SB + r * BSTRIDE + c4 * 4],
                           &Bg[(size_t)(k0 + r) * ldb + col0 + c4 * 4]);
            }
        }
    };

    const uint32_t as_base = (uint32_t)__cvta_generic_to_shared(As);
    const uint32_t bs_base = (uint32_t)__cvta_generic_to_shared(Bs);
    const int a_thr_off = (wm + ((lane >> 3) & 1) * 8 + (lane & 7)) * ASTRIDE
                        + ((lane >> 4) ? 4 : 0);
    const int b4_off = TRANSB
        ? (wn + ((lane >> 4) << 3) + (lane & 7)) * BSTRIDE + (((lane >> 3) & 1) << 2)
        : 0;

    float acc[AM][BNT][4];
#pragma unroll
    for (int i = 0; i < AM; i++)
#pragma unroll
        for (int j = 0; j < BNT; j++)
#pragma unroll
            for (int q = 0; q < 4; q++) acc[i][j][q] = 0.f;

    const int KT = K / BK;
    int fetch = 0;
    for (; fetch < STAGES - 1; fetch++) {
        copyA(fetch, fetch * BK);
        copyB(fetch, fetch * BK);
        cp_commit();
    }

    for (int kt = 0; kt < KT; kt++) {
        cp_wait<STAGES - 2>();
        __syncthreads();
        if (fetch < KT) {
            copyA(fetch % STAGES, fetch * BK);
            copyB(fetch % STAGES, fetch * BK);
            fetch++;
        }
        cp_commit();

        const int buf = kt % STAGES;
        const float* Bsb = &Bs[buf * SB];
#pragma unroll
        for (int ks = 0; ks < BK; ks += 8) {
            uint32_t af[AM][4];
            uint32_t bf[BNT][2];
#pragma unroll
            for (int i = 0; i < AM; i++) {
                uint32_t addr = as_base + 4u * (buf * SA + a_thr_off + i * 16 * ASTRIDE + ks);
                ldsm_x4(af[i], addr);
                if (CVTA) {
                    af[i][0] = f2tf(af[i][0]); af[i][1] = f2tf(af[i][1]);
                    af[i][2] = f2tf(af[i][2]); af[i][3] = f2tf(af[i][3]);
                }
            }
            if (TRANSB) {
#pragma unroll
                for (int j = 0; j < BNT; j += 2) {
                    uint32_t r[4];
                    ldsm_x4(r, bs_base + 4u * (buf * SB + b4_off + j * 8 * BSTRIDE + ks));
                    bf[j][0] = r[0]; bf[j][1] = r[1];
                    bf[j + 1][0] = r[2]; bf[j + 1][1] = r[3];
                }
            } else {
#pragma unroll
                for (int j = 0; j < BNT; j++) {
                    int n = wn + j * 8 + grp;
                    bf[j][0] = __float_as_uint(Bsb[(ks + tig) * BSTRIDE + n]);
                    bf[j][1] = __float_as_uint(Bsb[(ks + tig + 4) * BSTRIDE + n]);
                }
            }
#pragma unroll
            for (int i = 0; i < AM; i++)
#pragma unroll
                for (int j = 0; j < BNT; j++)
                    mma_tf32(acc[i][j], af[i], bf[j]);
        }
    }

#pragma unroll
    for (int i = 0; i < AM; i++) {
        int r1 = row0 + wm + i * 16 + grp;
        int r2 = r1 + 8;
#pragma unroll
        for (int j = 0; j < BNT; j++) {
            int cc = col0 + wn + j * 8 + tig * 2;
            float b0v = 0.f, b1v = 0.f;
            if (BIAS) { b0v = biasSel[cc]; b1v = biasSel[cc + 1]; }
            float v0 = acc[i][j][0] * scale + b0v;
            float v1 = acc[i][j][1] * scale + b1v;
            float v2 = acc[i][j][2] * scale + b0v;
            float v3 = acc[i][j][3] * scale + b1v;
            if (RELU) {
                v0 = fmaxf(v0, 0.f); v1 = fmaxf(v1, 0.f);
                v2 = fmaxf(v2, 0.f); v3 = fmaxf(v3, 0.f);
            }
            if (ROUT) {
                v0 = tf32r(v0); v1 = tf32r(v1); v2 = tf32r(v2); v3 = tf32r(v3);
            }
            *(float2*)&Cg[(size_t)r1 * ldc + cc] = make_float2(v0, v1);
            *(float2*)&Cg[(size_t)r2 * ldc + cc] = make_float2(v2, v3);
        }
    }
}

// ---------------- residual add + layernorm (dual output) ----------------------
__global__ void add_ln_kernel(const float* __restrict__ a,
                              const float* __restrict__ bres,
                              const float* __restrict__ g,
                              const float* __restrict__ be,
                              float* __restrict__ out,
                              float* __restrict__ out_r) {
    const size_t row = blockIdx.x;
    const float4* pa = (const float4*)(a + row * Dd);
    const float4* pb = (const float4*)(bres + row * Dd);
    float4* po = (float4*)(out + row * Dd);
    const int tid = threadIdx.x;  // 256
    __shared__ float red[8];
    float4 va = pa[tid], vb = pb[tid];
    float4 v = make_float4(va.x + vb.x, va.y + vb.y, va.z + vb.z, va.w + vb.w);
    float s = v.x + v.y + v.z + v.w;
#pragma unroll
    for (int o = 16; o > 0; o >>= 1) s += __shfl_xor_sync(~0u, s, o);
    if ((tid & 31) == 0) red[tid >> 5] = s;
    __syncthreads();
    s = red[tid & 7];
#pragma unroll
    for (int o = 4; o > 0; o >>= 1) s += __shfl_xor_sync(~0u, s, o);
    const float mu = s * (1.f / Dd);
    float q = (v.x - mu) * (v.x - mu) + (v.y - mu) * (v.y - mu)
            + (v.z - mu) * (v.z - mu) + (v.w - mu) * (v.w - mu);
#pragma unroll
    for (int o = 16; o > 0; o >>= 1) q += __shfl_xor_sync(~0u, q, o);
    __syncthreads();
    if ((tid & 31) == 0) red[tid >> 5] = q;
    __syncthreads();
    q = red[tid & 7];
#pragma unroll
    for (int o = 4; o > 0; o >>= 1) q += __shfl_xor_sync(~0u, q, o);
    const float inv = rsqrtf(q * (1.f / Dd) + EPSl);
    float4 vg = ((const float4*)g)[tid], vbe = ((const float4*)be)[tid];
    float4 r = make_float4((v.x - mu) * inv * vg.x + vbe.x,
                           (v.y - mu) * inv * vg.y + vbe.y,
                           (v.z - mu) * inv * vg.z + vbe.z,
                           (v.w - mu) * inv * vg.w + vbe.w);
    po[tid] = r;
    if (out_r) {
        float4 rr = make_float4(tf32r(r.x), tf32r(r.y), tf32r(r.z), tf32r(r.w));
        ((float4*)(out_r + row * Dd))[tid] = rr;
    }
}

// ---------------- launch -------------------------------------------------------
extern "C" void kernel_launch(void* const* d_in, const int* in_sizes, int n_in,
                              void* d_out, int out_size) {
    const float* x  = (const float*)d_in[0];
    const float* Wq = (const float*)d_in[1];
    const float* bq = (const float*)d_in[2];
    const float* Wk = (const float*)d_in[3];
    const float* bk = (const float*)d_in[4];
    const float* Wv = (const float*)d_in[5];
    const float* bv = (const float*)d_in[6];
    const float* Wo = (const float*)d_in[7];
    const float* bo = (const float*)d_in[8];
    const float* W1 = (const float*)d_in[9];
    const float* b1 = (const float*)d_in[10];
    const float* W2 = (const float*)d_in[11];
    const float* b2 = (const float*)d_in[12];
    const float* g1 = (const float*)d_in[13];
    const float* be1 = (const float*)d_in[14];
    const float* g2 = (const float*)d_in[15];
    const float* be2 = (const float*)d_in[16];

    float* q;    cudaGetSymbolAddress((void**)&q,    g_q);
    float* k;    cudaGetSymbolAddress((void**)&k,    g_k);
    float* v;    cudaGetSymbolAddress((void**)&v,    g_v);
    float* ctx;  cudaGetSymbolAddress((void**)&ctx,  g_ctx);
    float* t1;   cudaGetSymbolAddress((void**)&t1,   g_t1);
    float* x1;   cudaGetSymbolAddress((void**)&x1,   g_x1);
    float* x1r;  cudaGetSymbolAddress((void**)&x1r,  g_x1r);
    float* xr;   cudaGetSymbolAddress((void**)&xr,   g_xr);
    float* ffh;  cudaGetSymbolAddress((void**)&ffh,  g_ffh);
    float* wqt;  cudaGetSymbolAddress((void**)&wqt,  g_wqt);
    float* wkt;  cudaGetSymbolAddress((void**)&wkt,  g_wkt);
    float* wvt;  cudaGetSymbolAddress((void**)&wvt,  g_wvt);
    float* wot;  cudaGetSymbolAddress((void**)&wot,  g_wot);
    float* w1t;  cudaGetSymbolAddress((void**)&w1t,  g_w1t);
    float* w2t;  cudaGetSymbolAddress((void**)&w2t,  g_w2t);
    float* attn_fb; cudaGetSymbolAddress((void**)&attn_fb, g_attn_fb);
    float* x_fb;    cudaGetSymbolAddress((void**)&x_fb,    g_x_fb);

    float* out_x;
    float* out_attn;
    const size_t osz = (size_t)out_size;
    if (osz >= X_ELEMS + ATT_ELEMS) {
        out_x = (float*)d_out;
        out_attn = (float*)d_out + X_ELEMS;
    } else if (osz == ATT_ELEMS) {
        out_x = x_fb;
        out_attn = (float*)d_out;
    } else {
        out_x = (float*)d_out;
        out_attn = attn_fb;
    }

    const int M = Bb * Ss;  // 4096
    dim3 blk(256);

    const int smem_projT = 3 * (128 * 36 + 128 * 36) * 4;  // 110,592 B (BK=32)
    const int smem_ctx   = 6 * (128 * 20 + 16 * 68) * 4;   // 87,552 B  (BK=16)
    const int smem_fused = 3 * 128 * 68 * 4;                // 104,448 B

    auto* kqkv   = tf32_gemm<128,128,64,32,true, true,false,3,false,true, 3,32>;
    auto* kproj  = tf32_gemm<128,128,64,32,true, true,false,0,false,false,3,32>;
    auto* kprojr = tf32_gemm<128,128,64,32,true, true,true, 0,false,true, 3,32>;
    auto* kctx   = tf32_gemm<128,64,64,16,false,false,false,2,true, true, 6,16>;
    cudaFuncSetAttribute(kqkv,   cudaFuncAttributeMaxDynamicSharedMemorySize, smem_projT);
    cudaFuncSetAttribute(kproj,  cudaFuncAttributeMaxDynamicSharedMemorySize, smem_projT);
    cudaFuncSetAttribute(kprojr, cudaFuncAttributeMaxDynamicSharedMemorySize, smem_projT);
    cudaFuncSetAttribute(kctx,   cudaFuncAttributeMaxDynamicSharedMemorySize, smem_ctx);
    cudaFuncSetAttribute(fused_scores_softmax,
                         cudaFuncAttributeMaxDynamicSharedMemorySize, smem_fused);

    // round x; round+transpose all 6 weights in ONE launch
    round_kernel<<<(X_ELEMS / 4 + 255) / 256, blk>>>((const float4*)x, (float4*)xr, X_ELEMS / 4);
    {
        RtJobs jb;
        const float* ins[6] = { Wq, Wk, Wv, Wo, W1, W2 };
        float* outs[6]      = { wqt, wkt, wvt, wot, w1t, w2t };
        int Rs[6] = { Dd, Dd, Dd, Dd, Dd, DFFf };
        int Cs[6] = { Dd, Dd, Dd, Dd, DFFf, Dd };
        int base = 0;
        for (int j = 0; j < 6; j++) {
            jb.in[j] = ins[j]; jb.out[j] = outs[j];
            jb.R[j] = Rs[j]; jb.C[j] = Cs[j]; jb.base[j] = base;
            base += (Rs[j] / 32) * (Cs[j] / 32);
        }
        dim3 tblk(32, 8);
        rt_batch_kernel<<<base, tblk>>>(jb);
    }

    // QKV projections (transposed weights [n][k], row stride Dd)
    kqkv<<<dim3(Dd/128, M/128, 3), blk, smem_projT>>>(
        xr, wqt, wkt, wvt, bq, bk, bv, q, k, v, Dd, Dd, Dd, Dd, 1.f);

    // fused scores + softmax
    fused_scores_softmax<<<dim3(Ss/16, Bb*Hh), 256, smem_fused>>>(q, k, out_attn);

    // ctx: attn (unrounded -> CVTA) @ V (rounded); 6-stage pipeline
    kctx<<<dim3(1, Ss/128, Bb*Hh), blk, smem_ctx>>>(
        out_attn, v, nullptr, nullptr, nullptr, nullptr, nullptr,
        ctx, nullptr, nullptr, Ss, Ss, Dd, Dd, 1.f);

    // output projection + LN1
    kproj<<<dim3(Dd/128, M/128), blk, smem_projT>>>(
        ctx, wot, nullptr, nullptr, bo, nullptr, nullptr,
        t1, nullptr, nullptr, Dd, Dd, Dd, Dd, 1.f);
    add_ln_kernel<<<M, blk>>>(x, t1, g1, be1, x1, x1r);

    // FFN1: w1t is [DFF][Dd] -> ldb = Dd
    kprojr<<<dim3(DFFf/128, M/128), blk, smem_projT>>>(
        x1r, w1t, nullptr, nullptr, b1, nullptr, nullptr,
        ffh, nullptr, nullptr, Dd, Dd, Dd, DFFf, 1.f);
    // FFN2: w2t is [Dd][DFFf] -> ldb = DFFf
    kproj<<<dim3(Dd/128, M/128), blk, smem_projT>>>(
        ffh, w2t, nullptr, nullptr, b2, nullptr, nullptr,
        t1, nullptr, nullptr, DFFf, DFFf, DFFf, Dd, 1.f);
    add_ln_kernel<<<M, blk>>>(x1, t1, g2, be2, out_x, nullptr);
}

// round 15
// speedup vs baseline: 1.2136x; 1.0082x over previous
#include <cuda_runtime.h>
#include <math_constants.h>
#include <cstdint>

#define Bb 4
#define Ss 1024
#define Dd 1024
#define Hh 16
#define DKk 64
#define DFFf 4096
#define EPSl 1e-5f

#define X_ELEMS   ((size_t)Bb * Ss * Dd)
#define ATT_ELEMS ((size_t)Bb * Hh * Ss * Ss)

// ---------------- scratch ----------------
__device__ float g_q[X_ELEMS];
__device__ float g_k[X_ELEMS];
__device__ float g_v[X_ELEMS];
__device__ float g_ctx[X_ELEMS];
__device__ float g_t1[X_ELEMS];
__device__ float g_x1[X_ELEMS];
__device__ float g_x1r[X_ELEMS];
__device__ float g_xr[X_ELEMS];
__device__ float g_ffh[(size_t)Bb * Ss * DFFf];
__device__ float g_wqt[(size_t)Dd * Dd];
__device__ float g_wkt[(size_t)Dd * Dd];
__device__ float g_wvt[(size_t)Dd * Dd];
__device__ float g_wot[(size_t)Dd * Dd];
__device__ float g_w1t[(size_t)Dd * DFFf];
__device__ float g_w2t[(size_t)Dd * DFFf];
__device__ float g_attn_fb[ATT_ELEMS];
__device__ float g_x_fb[X_ELEMS];

// ---------------- helpers ----------------
__device__ __forceinline__ void cp_async16(void* smem_dst, const void* gsrc) {
    uint32_t s = (uint32_t)__cvta_generic_to_shared(smem_dst);
    asm volatile("cp.async.cg.shared.global [%0], [%1], 16;" :: "r"(s), "l"(gsrc));
}
__device__ __forceinline__ void cp_commit() {
    asm volatile("cp.async.commit_group;");
}
template<int N>
__device__ __forceinline__ void cp_wait() {
    asm volatile("cp.async.wait_group %0;" :: "n"(N));
}
__device__ __forceinline__ uint32_t f2tf(uint32_t x) {
    uint32_t r;
    asm("cvt.rna.tf32.f32 %0, %1;" : "=r"(r) : "f"(__uint_as_float(x)));
    return r;
}
__device__ __forceinline__ float tf32r(float x) {
    return __uint_as_float(f2tf(__float_as_uint(x)));
}
__device__ __forceinline__ void ldsm_x4(uint32_t r[4], uint32_t saddr) {
    asm volatile("ldmatrix.sync.aligned.m8n8.x4.shared.b16 {%0,%1,%2,%3}, [%4];"
                 : "=r"(r[0]), "=r"(r[1]), "=r"(r[2]), "=r"(r[3]) : "r"(saddr));
}
__device__ __forceinline__ void mma_tf32(float c[4], const uint32_t a[4], const uint32_t b[2]) {
    asm volatile(
        "mma.sync.aligned.m16n8k8.row.col.f32.tf32.tf32.f32 "
        "{%0,%1,%2,%3}, {%4,%5,%6,%7}, {%8,%9}, {%0,%1,%2,%3};"
        : "+f"(c[0]), "+f"(c[1]), "+f"(c[2]), "+f"(c[3])
        : "r"(a[0]), "r"(a[1]), "r"(a[2]), "r"(a[3]), "r"(b[0]), "r"(b[1]));
}
__device__ __forceinline__ void stcs2(float* p, float a, float b) {
    asm volatile("st.global.cs.v2.f32 [%0], {%1, %2};" :: "l"(p), "f"(a), "f"(b) : "memory");
}

// ---------------- round x to tf32 ----------------
__global__ void round_kernel(const float4* __restrict__ in, float4* __restrict__ out, int n4) {
    int i = blockIdx.x * blockDim.x + threadIdx.x;
    if (i >= n4) return;
    float4 v = in[i];
    v.x = tf32r(v.x); v.y = tf32r(v.y); v.z = tf32r(v.z); v.w = tf32r(v.w);
    out[i] = v;
}

// ---------------- batched round + transpose: 6 weights in one launch ----------
struct RtJobs {
    const float* in[6];
    float* out[6];
    int R[6];
    int C[6];
    int base[6];
};
__global__ void rt_batch_kernel(RtJobs jb) {
    __shared__ float tile[32][33];
    const int bx = blockIdx.x;
    int j = 0;
#pragma unroll
    for (int t = 1; t < 6; t++) if (bx >= jb.base[t]) j = t;
    const int tiles_x = jb.C[j] >> 5;
    const int t = bx - jb.base[j];
    const int c0 = (t % tiles_x) * 32;
    const int r0 = (t / tiles_x) * 32;
    const float* in = jb.in[j];
    float* out = jb.out[j];
    const int R = jb.R[j], C = jb.C[j];
    const int tx = threadIdx.x, ty = threadIdx.y;   // 32 x 8
#pragma unroll
    for (int i = 0; i < 4; i++)
        tile[ty + i * 8][tx] = in[(size_t)(r0 + ty + i * 8) * C + c0 + tx];
    __syncthreads();
#pragma unroll
    for (int i = 0; i < 4; i++)
        out[(size_t)(c0 + ty + i * 8) * R + r0 + tx] = tf32r(tile[tx][ty + i * 8]);
}

// ===== fused scores + softmax: 256 thr / 16 q-rows per CTA ====================
__global__ void __launch_bounds__(256, 2)
fused_scores_softmax(const float* __restrict__ Q, const float* __restrict__ K,
                     float* __restrict__ attn) {
    constexpr int CN = 128;
    constexpr int KST = 68;
    constexpr int NCH = Ss / CN;  // 8
    constexpr int SK = 3;

    extern __shared__ float Ksm[];    // [SK][CN][KST]
    __shared__ float red[16][8];

    const int z = blockIdx.y;
    const int b = z >> 4, h = z & 15;
    const int q0 = blockIdx.x * 16;
    const float* Qb = Q + (size_t)b * Ss * Dd + (size_t)h * DKk;
    const float* Kb = K + (size_t)b * Ss * Dd + (size_t)h * DKk;
    float* Ob = attn + (size_t)z * Ss * Ss;

    const int tid = threadIdx.x;
    const int warp = tid >> 5, lane = tid & 31;
    const int grp = lane >> 2, tig = lane & 3;
    const int wcol = warp;
    const int r0 = q0;

    uint32_t qf[8][4];
#pragma unroll
    for (int ks = 0; ks < 8; ks++) {
        const float* p0 = &Qb[(size_t)(r0 + grp) * Dd + ks * 8 + tig];
        const float* p1 = &Qb[(size_t)(r0 + grp + 8) * Dd + ks * 8 + tig];
        qf[ks][0] = __float_as_uint(p0[0]);
        qf[ks][1] = __float_as_uint(p1[0]);
        qf[ks][2] = __float_as_uint(p0[4]);
        qf[ks][3] = __float_as_uint(p1[4]);
    }

    auto copyK = [&](int stage, int chunk) {
#pragma unroll
        for (int i = 0; i < 8; i++) {
            int flat = tid + i * 256;
            int r = flat >> 4, c4 = flat & 15;
            cp_async16(&Ksm[stage * CN * KST + r * KST + c4 * 4],
                       &Kb[(size_t)(chunk * CN + r) * Dd + c4 * 4]);
        }
    };

    const uint32_t ksm_base = (uint32_t)__cvta_generic_to_shared(Ksm);
    const int kf_off = (wcol * 16 + ((lane >> 4) << 3) + (lane & 7)) * KST
                     + (((lane >> 3) & 1) << 2);

    float acc[NCH][2][4];
#pragma unroll
    for (int c = 0; c < NCH; c++)
#pragma unroll
        for (int j = 0; j < 2; j++)
#pragma unroll
            for (int q = 0; q < 4; q++) acc[c][j][q] = 0.f;

    int fetch = 0;
    for (; fetch < SK - 1; fetch++) { copyK(fetch, fetch); cp_commit(); }

    for (int c = 0; c < NCH; c++) {
        cp_wait<SK - 2>();
        __syncthreads();
        if (fetch < NCH) { copyK(fetch % SK, fetch); fetch++; }
        cp_commit();
        const uint32_t cb = ksm_base + 4u * ((c % SK) * CN * KST + kf_off);
#pragma unroll
        for (int ks = 0; ks < 8; ks++) {
            uint32_t r[4];
            ldsm_x4(r, cb + 4u * (ks * 8));
            uint32_t bf0[2] = { r[0], r[1] };
            uint32_t bf1[2] = { r[2], r[3] };
            mma_tf32(acc[c][0], qf[ks], bf0);
            mma_tf32(acc[c][1], qf[ks], bf1);
        }
    }
    __syncthreads();

    float m0 = -CUDART_INF_F, m1 = -CUDART_INF_F;
#pragma unroll
    for (int c = 0; c < NCH; c++)
#pragma unroll
        for (int j = 0; j < 2; j++) {
            acc[c][j][0] *= 0.125f; acc[c][j][1] *= 0.125f;
            acc[c][j][2] *= 0.125f; acc[c][j][3] *= 0.125f;
            m0 = fmaxf(m0, fmaxf(acc[c][j][0], acc[c][j][1]));
            m1 = fmaxf(m1, fmaxf(acc[c][j][2], acc[c][j][3]));
        }
    m0 = fmaxf(m0, __shfl_xor_sync(~0u, m0, 1));
    m0 = fmaxf(m0, __shfl_xor_sync(~0u, m0, 2));
    m1 = fmaxf(m1, __shfl_xor_sync(~0u, m1, 1));
    m1 = fmaxf(m1, __shfl_xor_sync(~0u, m1, 2));
    if (tig == 0) {
        red[grp][wcol] = m0;
        red[grp + 8][wcol] = m1;
    }
    __syncthreads();
    m0 = red[grp][0];
    m1 = red[grp + 8][0];
#pragma unroll
    for (int w = 1; w < 8; w++) {
        m0 = fmaxf(m0, red[grp][w]);
        m1 = fmaxf(m1, red[grp + 8][w]);
    }
    __syncthreads();

    float s0 = 0.f, s1 = 0.f;
#pragma unroll
    for (int c = 0; c < NCH; c++)
#pragma unroll
        for (int j = 0; j < 2; j++) {
            acc[c][j][0] = __expf(acc[c][j][0] - m0);
            acc[c][j][1] = __expf(acc[c][j][1] - m0);
            acc[c][j][2] = __expf(acc[c][j][2] - m1);
            acc[c][j][3] = __expf(acc[c][j][3] - m1);
            s0 += acc[c][j][0] + acc[c][j][1];
            s1 += acc[c][j][2] + acc[c][j][3];
        }
    s0 += __shfl_xor_sync(~0u, s0, 1);
    s0 += __shfl_xor_sync(~0u, s0, 2);
    s1 += __shfl_xor_sync(~0u, s1, 1);
    s1 += __shfl_xor_sync(~0u, s1, 2);
    if (tig == 0) {
        red[grp][wcol] = s0;
        red[grp + 8][wcol] = s1;
    }
    __syncthreads();
    s0 = 0.f; s1 = 0.f;
#pragma unroll
    for (int w = 0; w < 8; w++) {
        s0 += red[grp][w];
        s1 += red[grp + 8][w];
    }
    const float i0 = 1.f / s0, i1 = 1.f / s1;

    float* O0 = &Ob[(size_t)(r0 + grp) * Ss];
    float* O1 = &Ob[(size_t)(r0 + grp + 8) * Ss];
#pragma unroll
    for (int c = 0; c < NCH; c++)
#pragma unroll
        for (int j = 0; j < 2; j++) {
            int col = c * 128 + wcol * 16 + j * 8 + tig * 2;
            stcs2(&O0[col], acc[c][j][0] * i0, acc[c][j][1] * i0);
            stcs2(&O1[col], acc[c][j][2] * i1, acc[c][j][3] * i1);
        }
}

// MODE: 0 = plain GEMM. 2 = ctx. 3 = QKV batched.
// TRANSB: B stored [n][k]. CVTA: round A fragments. ROUT: round output.
// STAGES: cp.async depth. BK: k-chunk per stage (multiple of 8).
template<int BM, int BN, int WM, int WN, bool TRANSB, bool BIAS, bool RELU,
         int MODE, bool CVTA, bool ROUT, int STAGES, int BK>
__global__ void __launch_bounds__(256)
tf32_gemm(const float* __restrict__ A,
          const float* __restrict__ B0, const float* __restrict__ B1p, const float* __restrict__ B2p,
          const float* __restrict__ bias0, const float* __restrict__ bias1, const float* __restrict__ bias2,
          float* __restrict__ C0, float* __restrict__ C1p, float* __restrict__ C2p,
          int K, int lda, int ldb, int ldc, float scale) {
    constexpr int WCOLS = BN / WN;
    constexpr int AM = WM / 16;
    constexpr int BNT = WN / 8;
    constexpr int ASTRIDE = BK + 4;
    constexpr int BSTRIDE = TRANSB ? (BK + 4) : (BN + 4);
    constexpr int SA = BM * ASTRIDE;
    constexpr int SB = TRANSB ? (BN * ASTRIDE) : (BK * (BN + 4));
    constexpr int LDA_V = BM * BK / (4 * 256);
    constexpr int LDB_V = (TRANSB ? BN * BK : BK * BN) / (4 * 256);
    constexpr int F4R = BK / 4;

    extern __shared__ float smem[];
    float* As = smem;
    float* Bs = smem + STAGES * SA;

    const int tid = threadIdx.x;
    const int warp = tid >> 5, lane = tid & 31;
    const int grp = lane >> 2, tig = lane & 3;
    const int wm = (warp / WCOLS) * WM;
    const int wn = (warp % WCOLS) * WN;
    const int row0 = blockIdx.y * BM;
    const int col0 = blockIdx.x * BN;
    const int z = blockIdx.z;

    const float* Bsel = B0;
    const float* biasSel = bias0;
    float* Csel = C0;
    if (MODE == 3) {
        if (z == 1) { Bsel = B1p; biasSel = bias1; Csel = C1p; }
        else if (z == 2) { Bsel = B2p; biasSel = bias2; Csel = C2p; }
    }

    size_t offA = 0, offB = 0, offC = 0;
    if (MODE == 2) {
        size_t ho = (size_t)(z >> 4) * Ss * Dd + (size_t)(z & 15) * DKk;
        offA = (size_t)z * Ss * Ss; offB = ho; offC = ho;
    }
    const float* Ag = A + offA;
    const float* Bg = Bsel + offB;
    float* Cg = Csel + offC;

    auto copyA = [&](int stage, int k0) {
#pragma unroll
        for (int i = 0; i < LDA_V; i++) {
            int flat = tid + i * 256;
            int r = flat / F4R, c4 = flat % F4R;
            cp_async16(&As[stage * SA + r * ASTRIDE + c4 * 4],
                       &Ag[(size_t)(row0 + r) * lda + k0 + c4 * 4]);
        }
    };
    auto copyB = [&](int stage, int k0) {
#pragma unroll
        for (int i = 0; i < LDB_V; i++) {
            int flat = tid + i * 256;
            if (TRANSB) {
                int n = flat / F4R, c4 = flat % F4R;
                cp_async16(&Bs[stage * SB + n * BSTRIDE + c4 * 4],
                           &Bg[(size_t)(col0 + n) * ldb + k0 + c4 * 4]);
            } else {
                constexpr int C4 = BN / 4;
                int r = flat / C4, c4 = flat % C4;
                cp_async16(&Bs[stage * SB + r * BSTRIDE + c4 * 4],
                           &Bg[(size_t)(k0 + r) * ldb + col0 + c4 * 4]);
            }
        }
    };

    const uint32_t as_base = (uint32_t)__cvta_generic_to_shared(As);
    const uint32_t bs_base = (uint32_t)__cvta_generic_to_shared(Bs);
    const int a_thr_off = (wm + ((lane >> 3) & 1) * 8 + (lane & 7)) * ASTRIDE
                        + ((lane >> 4) ? 4 : 0);
    const int b4_off = TRANSB
        ? (wn + ((lane >> 4) << 3) + (lane & 7)) * BSTRIDE + (((lane >> 3) & 1) << 2)
        : 0;

    float acc[AM][BNT][4];
#pragma unroll
    for (int i = 0; i < AM; i++)
#pragma unroll
        for (int j = 0; j < BNT; j++)
#pragma unroll
            for (int q = 0; q < 4; q++) acc[i][j][q] = 0.f;

    const int KT = K / BK;
    int fetch = 0;
    for (; fetch < STAGES - 1; fetch++) {
        copyA(fetch, fetch * BK);
        copyB(fetch, fetch * BK);
        cp_commit();
    }

    for (int kt = 0; kt < KT; kt++) {
        cp_wait<STAGES - 2>();
        __syncthreads();
        if (fetch < KT) {
            copyA(fetch % STAGES, fetch * BK);
            copyB(fetch % STAGES, fetch * BK);
            fetch++;
        }
        cp_commit();

        const int buf = kt % STAGES;
        const float* Bsb = &Bs[buf * SB];
#pragma unroll
        for (int ks = 0; ks < BK; ks += 8) {
            uint32_t af[AM][4];
            uint32_t bf[BNT][2];
#pragma unroll
            for (int i = 0; i < AM; i++) {
                uint32_t addr = as_base + 4u * (buf * SA + a_thr_off + i * 16 * ASTRIDE + ks);
                ldsm_x4(af[i], addr);
                if (CVTA) {
                    af[i][0] = f2tf(af[i][0]); af[i][1] = f2tf(af[i][1]);
                    af[i][2] = f2tf(af[i][2]); af[i][3] = f2tf(af[i][3]);
                }
            }
            if (TRANSB) {
#pragma unroll
                for (int j = 0; j < BNT; j += 2) {
                    uint32_t r[4];
                    ldsm_x4(r, bs_base + 4u * (buf * SB + b4_off + j * 8 * BSTRIDE + ks));
                    bf[j][0] = r[0]; bf[j][1] = r[1];
                    bf[j + 1][0] = r[2]; bf[j + 1][1] = r[3];
                }
            } else {
#pragma unroll
                for (int j = 0; j < BNT; j++) {
                    int n = wn + j * 8 + grp;
                    bf[j][0] = __float_as_uint(Bsb[(ks + tig) * BSTRIDE + n]);
                    bf[j][1] = __float_as_uint(Bsb[(ks + tig + 4) * BSTRIDE + n]);
                }
            }
#pragma unroll
            for (int i = 0; i < AM; i++)
#pragma unroll
                for (int j = 0; j < BNT; j++)
                    mma_tf32(acc[i][j], af[i], bf[j]);
        }
    }

#pragma unroll
    for (int i = 0; i < AM; i++) {
        int r1 = row0 + wm + i * 16 + grp;
        int r2 = r1 + 8;
#pragma unroll
        for (int j = 0; j < BNT; j++) {
            int cc = col0 + wn + j * 8 + tig * 2;
            float b0v = 0.f, b1v = 0.f;
            if (BIAS) { b0v = biasSel[cc]; b1v = biasSel[cc + 1]; }
            float v0 = acc[i][j][0] * scale + b0v;
            float v1 = acc[i][j][1] * scale + b1v;
            float v2 = acc[i][j][2] * scale + b0v;
            float v3 = acc[i][j][3] * scale + b1v;
            if (RELU) {
                v0 = fmaxf(v0, 0.f); v1 = fmaxf(v1, 0.f);
                v2 = fmaxf(v2, 0.f); v3 = fmaxf(v3, 0.f);
            }
            if (ROUT) {
                v0 = tf32r(v0); v1 = tf32r(v1); v2 = tf32r(v2); v3 = tf32r(v3);
            }
            *(float2*)&Cg[(size_t)r1 * ldc + cc] = make_float2(v0, v1);
            *(float2*)&Cg[(size_t)r2 * ldc + cc] = make_float2(v2, v3);
        }
    }
}

// ---------------- residual add + layernorm (dual output) ----------------------
__global__ void add_ln_kernel(const float* __restrict__ a,
                              const float* __restrict__ bres,
                              const float* __restrict__ g,
                              const float* __restrict__ be,
                              float* __restrict__ out,
                              float* __restrict__ out_r) {
    const size_t row = blockIdx.x;
    const float4* pa = (const float4*)(a + row * Dd);
    const float4* pb = (const float4*)(bres + row * Dd);
    float4* po = (float4*)(out + row * Dd);
    const int tid = threadIdx.x;  // 256
    __shared__ float red[8];
    float4 va = pa[tid], vb = pb[tid];
    float4 v = make_float4(va.x + vb.x, va.y + vb.y, va.z + vb.z, va.w + vb.w);
    float s = v.x + v.y + v.z + v.w;
#pragma unroll
    for (int o = 16; o > 0; o >>= 1) s += __shfl_xor_sync(~0u, s, o);
    if ((tid & 31) == 0) red[tid >> 5] = s;
    __syncthreads();
    s = red[tid & 7];
#pragma unroll
    for (int o = 4; o > 0; o >>= 1) s += __shfl_xor_sync(~0u, s, o);
    const float mu = s * (1.f / Dd);
    float q = (v.x - mu) * (v.x - mu) + (v.y - mu) * (v.y - mu)
            + (v.z - mu) * (v.z - mu) + (v.w - mu) * (v.w - mu);
#pragma unroll
    for (int o = 16; o > 0; o >>= 1) q += __shfl_xor_sync(~0u, q, o);
    __syncthreads();
    if ((tid & 31) == 0) red[tid >> 5] = q;
    __syncthreads();
    q = red[tid & 7];
#pragma unroll
    for (int o = 4; o > 0; o >>= 1) q += __shfl_xor_sync(~0u, q, o);
    const float inv = rsqrtf(q * (1.f / Dd) + EPSl);
    float4 vg = ((const float4*)g)[tid], vbe = ((const float4*)be)[tid];
    float4 r = make_float4((v.x - mu) * inv * vg.x + vbe.x,
                           (v.y - mu) * inv * vg.y + vbe.y,
                           (v.z - mu) * inv * vg.z + vbe.z,
                           (v.w - mu) * inv * vg.w + vbe.w);
    po[tid] = r;
    if (out_r) {
        float4 rr = make_float4(tf32r(r.x), tf32r(r.y), tf32r(r.z), tf32r(r.w));
        ((float4*)(out_r + row * Dd))[tid] = rr;
    }
}

// ---------------- launch -------------------------------------------------------
extern "C" void kernel_launch(void* const* d_in, const int* in_sizes, int n_in,
                              void* d_out, int out_size) {
    const float* x  = (const float*)d_in[0];
    const float* Wq = (const float*)d_in[1];
    const float* bq = (const float*)d_in[2];
    const float* Wk = (const float*)d_in[3];
    const float* bk = (const float*)d_in[4];
    const float* Wv = (const float*)d_in[5];
    const float* bv = (const float*)d_in[6];
    const float* Wo = (const float*)d_in[7];
    const float* bo = (const float*)d_in[8];
    const float* W1 = (const float*)d_in[9];
    const float* b1 = (const float*)d_in[10];
    const float* W2 = (const float*)d_in[11];
    const float* b2 = (const float*)d_in[12];
    const float* g1 = (const float*)d_in[13];
    const float* be1 = (const float*)d_in[14];
    const float* g2 = (const float*)d_in[15];
    const float* be2 = (const float*)d_in[16];

    float* q;    cudaGetSymbolAddress((void**)&q,    g_q);
    float* k;    cudaGetSymbolAddress((void**)&k,    g_k);
    float* v;    cudaGetSymbolAddress((void**)&v,    g_v);
    float* ctx;  cudaGetSymbolAddress((void**)&ctx,  g_ctx);
    float* t1;   cudaGetSymbolAddress((void**)&t1,   g_t1);
    float* x1;   cudaGetSymbolAddress((void**)&x1,   g_x1);
    float* x1r;  cudaGetSymbolAddress((void**)&x1r,  g_x1r);
    float* xr;   cudaGetSymbolAddress((void**)&xr,   g_xr);
    float* ffh;  cudaGetSymbolAddress((void**)&ffh,  g_ffh);
    float* wqt;  cudaGetSymbolAddress((void**)&wqt,  g_wqt);
    float* wkt;  cudaGetSymbolAddress((void**)&wkt,  g_wkt);
    float* wvt;  cudaGetSymbolAddress((void**)&wvt,  g_wvt);
    float* wot;  cudaGetSymbolAddress((void**)&wot,  g_wot);
    float* w1t;  cudaGetSymbolAddress((void**)&w1t,  g_w1t);
    float* w2t;  cudaGetSymbolAddress((void**)&w2t,  g_w2t);
    float* attn_fb; cudaGetSymbolAddress((void**)&attn_fb, g_attn_fb);
    float* x_fb;    cudaGetSymbolAddress((void**)&x_fb,    g_x_fb);

    float* out_x;
    float* out_attn;
    const size_t osz = (size_t)out_size;
    if (osz >= X_ELEMS + ATT_ELEMS) {
        out_x = (float*)d_out;
        out_attn = (float*)d_out + X_ELEMS;
    } else if (osz == ATT_ELEMS) {
        out_x = x_fb;
        out_attn = (float*)d_out;
    } else {
        out_x = (float*)d_out;
        out_attn = attn_fb;
    }

    const int M = Bb * Ss;  // 4096
    dim3 blk(256);

    const int smem_projT = 3 * (128 * 36 + 128 * 36) * 4;  // 110,592 B (BK=32)
    const int smem_ctx   = 4 * (128 * 36 + 32 * 68) * 4;   // 108,544 B (BK=32)
    const int smem_fused = 3 * 128 * 68 * 4;                // 104,448 B

    auto* kqkv   = tf32_gemm<128,128,64,32,true, true,false,3,false,true, 3,32>;
    auto* kproj  = tf32_gemm<128,128,64,32,true, true,false,0,false,false,3,32>;
    auto* kprojr = tf32_gemm<128,128,64,32,true, true,true, 0,false,true, 3,32>;
    auto* kctx   = tf32_gemm<128,64,64,16,false,false,false,2,true, true, 4,32>;
    cudaFuncSetAttribute(kqkv,   cudaFuncAttributeMaxDynamicSharedMemorySize, smem_projT);
    cudaFuncSetAttribute(kproj,  cudaFuncAttributeMaxDynamicSharedMemorySize, smem_projT);
    cudaFuncSetAttribute(kprojr, cudaFuncAttributeMaxDynamicSharedMemorySize, smem_projT);
    cudaFuncSetAttribute(kctx,   cudaFuncAttributeMaxDynamicSharedMemorySize, smem_ctx);
    cudaFuncSetAttribute(fused_scores_softmax,
                         cudaFuncAttributeMaxDynamicSharedMemorySize, smem_fused);

    // round x; round+transpose all 6 weights in ONE launch
    round_kernel<<<(X_ELEMS / 4 + 255) / 256, blk>>>((const float4*)x, (float4*)xr, X_ELEMS / 4);
    {
        RtJobs jb;
        const float* ins[6] = { Wq, Wk, Wv, Wo, W1, W2 };
        float* outs[6]      = { wqt, wkt, wvt, wot, w1t, w2t };
        int Rs[6] = { Dd, Dd, Dd, Dd, Dd, DFFf };
        int Cs[6] = { Dd, Dd, Dd, Dd, DFFf, Dd };
        int base = 0;
        for (int j = 0; j < 6; j++) {
            jb.in[j] = ins[j]; jb.out[j] = outs[j];
            jb.R[j] = Rs[j]; jb.C[j] = Cs[j]; jb.base[j] = base;
            base += (Rs[j] / 32) * (Cs[j] / 32);
        }
        dim3 tblk(32, 8);
        rt_batch_kernel<<<base, tblk>>>(jb);
    }

    // QKV projections (transposed weights [n][k], row stride Dd)
    kqkv<<<dim3(Dd/128, M/128, 3), blk, smem_projT>>>(
        xr, wqt, wkt, wvt, bq, bk, bv, q, k, v, Dd, Dd, Dd, Dd, 1.f);

    // fused scores + softmax (streaming attn stores)
    fused_scores_softmax<<<dim3(Ss/16, Bb*Hh), 256, smem_fused>>>(q, k, out_attn);

    // ctx: attn (unrounded -> CVTA) @ V (rounded); BK=32, 4 stages
    kctx<<<dim3(1, Ss/128, Bb*Hh), blk, smem_ctx>>>(
        out_attn, v, nullptr, nullptr, nullptr, nullptr, nullptr,
        ctx, nullptr, nullptr, Ss, Ss, Dd, Dd, 1.f);

    // output projection + LN1
    kproj<<<dim3(Dd/128, M/128), blk, smem_projT>>>(
        ctx, wot, nullptr, nullptr, bo, nullptr, nullptr,
        t1, nullptr, nullptr, Dd, Dd, Dd, Dd, 1.f);
    add_ln_kernel<<<M, blk>>>(x, t1, g1, be1, x1, x1r);

    // FFN1: w1t is [DFF][Dd] -> ldb = Dd
    kprojr<<<dim3(DFFf/128, M/128), blk, smem_projT>>>(
        x1r, w1t, nullptr, nullptr, b1, nullptr, nullptr,
        ffh, nullptr, nullptr, Dd, Dd, Dd, DFFf, 1.f);
    // FFN2: w2t is [Dd][DFFf] -> ldb = DFFf
    kproj<<<dim3(Dd/128, M/128), blk, smem_projT>>>(
        ffh, w2t, nullptr, nullptr, b2, nullptr, nullptr,
        t1, nullptr, nullptr, DFFf, DFFf, DFFf, Dd, 1.f);
    add_ln_kernel<<<M, blk>>>(x1, t1, g2, be2, out_x, nullptr);
}